// round 12
// baseline (speedup 1.0000x reference)
#include <cuda_runtime.h>
#include <cuda_bf16.h>
#include <cstdint>

#define NLV 127.0f

// ---------------- scratch (__device__ globals) -------------------------------
__device__ float g_maxes[8];                       // 0:x 1:w1 2:w2 3:w3 4:h1 5:h2
__device__ unsigned g_kflags[256];                 // per-K-chunk ready flags (w1q)
__device__ __nv_bfloat16 g_xq[512 * 9216];
__device__ __nv_bfloat16 g_w1q[4096 * 9216];
__device__ __nv_bfloat16 g_w2q[4096 * 4096];
__device__ __nv_bfloat16 g_w3q[1024 * 4096];       // padded 1000 -> 1024 rows
__device__ float g_h[512 * 4096];
__device__ __nv_bfloat16 g_hq[512 * 4096];
__device__ float g_part[4 * 512 * 1024];           // split-K partials for layer 3

// ---------------- helpers ----------------------------------------------------
__device__ __forceinline__ uint32_t smem_u32(const void* p) {
    uint32_t a;
    asm("{ .reg .u64 t; cvta.to.shared.u64 t, %1; cvt.u32.u64 %0, t; }"
        : "=r"(a) : "l"(p));
    return a;
}

__device__ __forceinline__ void cp_async16(uint32_t saddr, const void* g) {
    asm volatile("cp.async.cg.shared.global [%0], [%1], 16;"
                 :: "r"(saddr), "l"(g) : "memory");
}

#define CP_COMMIT() asm volatile("cp.async.commit_group;" ::: "memory")

__device__ __forceinline__ unsigned ld_acquire_gpu(const unsigned* p) {
    unsigned v;
    asm volatile("ld.acquire.gpu.u32 %0, [%1];" : "=r"(v) : "l"(p) : "memory");
    return v;
}

#define LDSM4(R, addr)                                                          \
    asm volatile("ldmatrix.sync.aligned.m8n8.x4.shared.b16 "                    \
                 "{%0, %1, %2, %3}, [%4];"                                      \
                 : "=r"((R)[0]), "=r"((R)[1]), "=r"((R)[2]), "=r"((R)[3])       \
                 : "r"(addr))

#define MMA16816(C, A, B0, B1)                                                  \
    asm volatile("mma.sync.aligned.m16n8k16.row.col.f32.bf16.bf16.f32 "         \
                 "{%0, %1, %2, %3}, {%4, %5, %6, %7}, {%8, %9}, "               \
                 "{%0, %1, %2, %3};"                                            \
                 : "+f"((C)[0]), "+f"((C)[1]), "+f"((C)[2]), "+f"((C)[3])       \
                 : "r"((A)[0]), "r"((A)[1]), "r"((A)[2]), "r"((A)[3]),          \
                   "r"(B0), "r"(B1))

// ---------------- small kernels ----------------------------------------------
__global__ void init_maxes_kernel() {
    if (threadIdx.x < 8) g_maxes[threadIdx.x] = 0.0f;
    if (threadIdx.x < 256) g_kflags[threadIdx.x] = 0u;
}

__global__ void maxabs_kernel(const float* __restrict__ src, int n4, int slot) {
    float m = 0.0f;
    const float4* s4 = (const float4*)src;
    for (int i = blockIdx.x * blockDim.x + threadIdx.x; i < n4;
         i += gridDim.x * blockDim.x) {
        float4 v = s4[i];
        m = fmaxf(m, fmaxf(fmaxf(fabsf(v.x), fabsf(v.y)),
                           fmaxf(fabsf(v.z), fabsf(v.w))));
    }
#pragma unroll
    for (int o = 16; o; o >>= 1) m = fmaxf(m, __shfl_xor_sync(0xFFFFFFFFu, m, o));
    __shared__ float sm[8];
    if ((threadIdx.x & 31) == 0) sm[threadIdx.x >> 5] = m;
    __syncthreads();
    if (threadIdx.x == 0) {
        float mm = sm[0];
#pragma unroll
        for (int w = 1; w < 8; w++) mm = fmaxf(mm, sm[w]);
        atomicMax((unsigned int*)&g_maxes[slot], __float_as_uint(mm));
    }
}

__device__ __forceinline__ uint32_t pack_bf16x2(float a, float b) {
    uint32_t lo = (uint32_t)__bfloat16_as_ushort(__float2bfloat16_rn(a));
    uint32_t hi = (uint32_t)__bfloat16_as_ushort(__float2bfloat16_rn(b));
    return lo | (hi << 16);
}

// quantize fp32 -> integer-valued bf16 (round-half-even, clip [lo,127])
__global__ void quant_kernel(const float* __restrict__ src,
                             __nv_bfloat16* __restrict__ dst,
                             int n4, int npad4, int slot, float lo) {
    float mx = g_maxes[slot];
    float scale = mx / NLV;
    if (!(scale > 0.0f)) scale = 1.0f;
    float inv = 1.0f / scale;
    for (int i = blockIdx.x * blockDim.x + threadIdx.x; i < npad4;
         i += gridDim.x * blockDim.x) {
        uint32_t w0 = 0u, w1 = 0u;
        if (i < n4) {
            float4 v = ((const float4*)src)[i];
            float q0 = fminf(fmaxf(rintf(v.x * inv), lo), NLV);
            float q1 = fminf(fmaxf(rintf(v.y * inv), lo), NLV);
            float q2 = fminf(fmaxf(rintf(v.z * inv), lo), NLV);
            float q3 = fminf(fmaxf(rintf(v.w * inv), lo), NLV);
            w0 = pack_bf16x2(q0, q1);
            w1 = pack_bf16x2(q2, q3);
        }
        ((uint2*)dst)[i] = make_uint2(w0, w1);
    }
}

// chunk-ordered w1 quantizer (producer for GEMM1). Grid-strides K-chunks of 64
// cols front-to-back; sets g_kflags[c] with release semantics when chunk done.
// rows=4096, K=9216 (2304 float4/row, 16 float4 per chunk-row).
__global__ void quant_w1_chunks_kernel(const float* __restrict__ src,
                                       __nv_bfloat16* __restrict__ dst) {
    float mx = g_maxes[1];
    float scale = mx / NLV;
    if (!(scale > 0.0f)) scale = 1.0f;
    float inv = 1.0f / scale;
    const int tid = threadIdx.x;
    const int q4 = tid & 15;        // float4 index within chunk-row
    const int r0 = tid >> 4;        // 0..15
    for (int c = blockIdx.x; c < 144; c += gridDim.x) {
#pragma unroll 4
        for (int it = 0; it < 256; it++) {
            int r = it * 16 + r0;
            size_t idx = (size_t)r * 2304 + c * 16 + q4;
            float4 v = ((const float4*)src)[idx];
            float a0 = fminf(fmaxf(rintf(v.x * inv), -NLV), NLV);
            float a1 = fminf(fmaxf(rintf(v.y * inv), -NLV), NLV);
            float a2 = fminf(fmaxf(rintf(v.z * inv), -NLV), NLV);
            float a3 = fminf(fmaxf(rintf(v.w * inv), -NLV), NLV);
            ((uint2*)dst)[idx] = make_uint2(pack_bf16x2(a0, a1),
                                            pack_bf16x2(a2, a3));
        }
        __threadfence();            // each thread's writes GPU-visible
        __syncthreads();            // all threads' fences done
        if (tid == 0)
            asm volatile("st.release.gpu.u32 [%0], %1;"
                         :: "l"(&g_kflags[c]), "r"(1u) : "memory");
    }
}

// split-K reduce for layer 3: sum 4 partials (fixed order), dequant + bias
__global__ void reduce3_kernel(const float* __restrict__ bias,
                               float* __restrict__ out) {
    int idx = blockIdx.x * blockDim.x + threadIdx.x;   // over 512*500 float2
    if (idx >= 512 * 500) return;
    int m = idx / 500;
    int n = (idx % 500) * 2;
    const float* p = g_part + m * 1024 + n;
    float s0 = 0.0f, s1 = 0.0f;
#pragma unroll
    for (int k = 0; k < 4; k++) {
        float2 v = *(const float2*)(p + k * (512 * 1024));
        s0 += v.x;
        s1 += v.y;
    }
    const float bs = (g_maxes[5] / NLV) * (g_maxes[3] / NLV);
    float o0 = s0 * bs + rintf(bias[n] / bs) * bs;
    float o1 = s1 * bs + rintf(bias[n + 1] / bs) * bs;
    *(float2*)(out + (size_t)m * 1000 + n) = make_float2(o0, o1);
}

// ---------------- HMMA GEMM ----------------------------------------------------
// C[M=512, Nout] = A[512,K] @ B[Npad,K]^T, bf16 in (integer-valued), fp32 accum.
// Tile 128x128x64, 3-stage cp.async pipeline, 8 warps (64x32 warp tiles).
// kflags != nullptr: spin (acquire) on per-K-chunk ready flag before prefetch.
constexpr int BM = 128, BN = 128, BK = 64, STAGES = 3, NTHREADS = 256;
constexpr int STAGE_BYTES = (BM * BK + BN * BK) * 2;   // 32768
constexpr int B_OFS = BM * BK * 2;                     // 16384

__global__ void __launch_bounds__(NTHREADS, 1)
gemm_q_kernel(const __nv_bfloat16* __restrict__ A,
              const __nv_bfloat16* __restrict__ B,
              const float* __restrict__ bias, float* __restrict__ out,
              const unsigned* kflags,
              int K, int Nout, int relu, int maxslot, int sa_slot, int sw_slot,
              int NK, int raw, int ostride) {
    extern __shared__ char smem_raw[];
    const uint32_t sb = smem_u32(smem_raw);

    const int tid = threadIdx.x;
    const int lane = tid & 31;
    const int wid = tid >> 5;
    const int wm = wid & 1;        // 2 m-blocks of 64
    const int wn = wid >> 1;       // 4 n-blocks of 32
    const int m0 = blockIdx.y * BM;
    const int n0 = blockIdx.x * BN;
    const size_t k_ofs = (size_t)blockIdx.z * NK * BK;
    float* outp = raw ? (out + (size_t)blockIdx.z * (512 * 1024)) : out;

    // ---- global->shared mapping: 2048 x 16B chunks / 256 threads = 8 each ----
    uint32_t s_st[8];
    const __nv_bfloat16* g_st[8];
#pragma unroll
    for (int i = 0; i < 8; i++) {
        int li = i * NTHREADS + tid;
        int isA = (li < 1024);
        int idx = li & 1023;
        int row = idx >> 3;            // 0..127
        int c = idx & 7;               // 16B chunk within 128B row
        s_st[i] = (uint32_t)((isA ? 0 : B_OFS) + row * 128 +
                             ((c ^ (row & 7)) << 4));
        g_st[i] = (isA ? (A + (size_t)(m0 + row) * K)
                       : (B + (size_t)(n0 + row) * K)) + k_ofs + c * 8;
    }

    // prologue loads
#pragma unroll
    for (int st = 0; st < 2; st++) {
        if (st < NK) {
            if (kflags) {
                if (tid == 0) while (ld_acquire_gpu(&kflags[st]) == 0) {}
                __syncthreads();
            }
            uint32_t base = sb + (uint32_t)(st % STAGES) * STAGE_BYTES;
#pragma unroll
            for (int i = 0; i < 8; i++)
                cp_async16(base + s_st[i], g_st[i] + (size_t)st * BK);
            CP_COMMIT();
        }
    }

    // ---- ldmatrix per-lane base addresses (within stage) ----
    const int r = lane & 7;
    const int g = lane >> 3;
    uint32_t a_row[4];
    int a_rx[4];
#pragma unroll
    for (int mi = 0; mi < 4; mi++) {
        int row = wm * 64 + mi * 16 + (g & 1) * 8 + r;
        a_row[mi] = (uint32_t)(row * 128);
        a_rx[mi] = row & 7;
    }
    uint32_t b_row[2];
    int b_rx[2];
#pragma unroll
    for (int p = 0; p < 2; p++) {
        int row = wn * 32 + p * 16 + (g >> 1) * 8 + r;
        b_row[p] = (uint32_t)(B_OFS + row * 128);
        b_rx[p] = row & 7;
    }

    float acc[4][4][4];
#pragma unroll
    for (int mi = 0; mi < 4; mi++)
#pragma unroll
        for (int ni = 0; ni < 4; ni++)
#pragma unroll
            for (int e = 0; e < 4; e++) acc[mi][ni][e] = 0.0f;

#pragma unroll 1
    for (int kc = 0; kc < NK; kc++) {
        if (kc + 2 < NK) {
            if (kflags) {
                if (tid == 0) while (ld_acquire_gpu(&kflags[kc + 2]) == 0) {}
                __syncthreads();
            }
            uint32_t base = sb + (uint32_t)((kc + 2) % STAGES) * STAGE_BYTES;
#pragma unroll
            for (int i = 0; i < 8; i++)
                cp_async16(base + s_st[i], g_st[i] + (size_t)(kc + 2) * BK);
            CP_COMMIT();
        }
        int rem = NK - 1 - kc;
        if (rem >= 2)      asm volatile("cp.async.wait_group 2;" ::: "memory");
        else if (rem == 1) asm volatile("cp.async.wait_group 1;" ::: "memory");
        else               asm volatile("cp.async.wait_group 0;" ::: "memory");
        __syncthreads();

        const uint32_t stage = sb + (uint32_t)(kc % STAGES) * STAGE_BYTES;
#pragma unroll
        for (int s = 0; s < 4; s++) {
            uint32_t af[4][4];
#pragma unroll
            for (int mi = 0; mi < 4; mi++) {
                int chunk = 2 * s + (g >> 1);
                LDSM4(af[mi], stage + a_row[mi] +
                              (uint32_t)((chunk ^ a_rx[mi]) << 4));
            }
            uint32_t bf[2][4];
#pragma unroll
            for (int p = 0; p < 2; p++) {
                int chunk = 2 * s + (g & 1);
                LDSM4(bf[p], stage + b_row[p] +
                             (uint32_t)((chunk ^ b_rx[p]) << 4));
            }
#pragma unroll
            for (int mi = 0; mi < 4; mi++) {
#pragma unroll
                for (int p = 0; p < 2; p++) {
                    MMA16816(acc[mi][2 * p],     af[mi], bf[p][0], bf[p][1]);
                    MMA16816(acc[mi][2 * p + 1], af[mi], bf[p][2], bf[p][3]);
                }
            }
        }
        __syncthreads();
    }

    // ---- epilogue ----
    if (raw) {
#pragma unroll
        for (int mi = 0; mi < 4; mi++) {
#pragma unroll
            for (int half = 0; half < 2; half++) {
                int m = m0 + wm * 64 + mi * 16 + (lane >> 2) + half * 8;
#pragma unroll
                for (int ni = 0; ni < 4; ni++) {
                    int n = n0 + wn * 32 + ni * 8 + (lane & 3) * 2;
                    *(float2*)(outp + (size_t)m * ostride + n) =
                        make_float2(acc[mi][ni][half * 2 + 0],
                                    acc[mi][ni][half * 2 + 1]);
                }
            }
        }
        return;
    }

    const float sa = g_maxes[sa_slot] / NLV;
    const float sw = g_maxes[sw_slot] / NLV;
    const float bs = sa * sw;
    float lmax = 0.0f;

    float bq[4][2];
#pragma unroll
    for (int ni = 0; ni < 4; ni++) {
        int n = n0 + wn * 32 + ni * 8 + (lane & 3) * 2;
#pragma unroll
        for (int e = 0; e < 2; e++)
            bq[ni][e] = (n + e < Nout) ? rintf(bias[n + e] / bs) * bs : 0.0f;
    }

#pragma unroll
    for (int mi = 0; mi < 4; mi++) {
#pragma unroll
        for (int half = 0; half < 2; half++) {
            int m = m0 + wm * 64 + mi * 16 + (lane >> 2) + half * 8;
#pragma unroll
            for (int ni = 0; ni < 4; ni++) {
                int n = n0 + wn * 32 + ni * 8 + (lane & 3) * 2;
                if (n < Nout) {
                    float v0 = acc[mi][ni][half * 2 + 0] * bs + bq[ni][0];
                    float v1 = acc[mi][ni][half * 2 + 1] * bs + bq[ni][1];
                    if (relu) { v0 = fmaxf(v0, 0.0f); v1 = fmaxf(v1, 0.0f); }
                    *(float2*)(outp + (size_t)m * ostride + n) =
                        make_float2(v0, v1);
                    lmax = fmaxf(lmax, fmaxf(fabsf(v0), fabsf(v1)));
                }
            }
        }
    }
    if (maxslot >= 0) {
#pragma unroll
        for (int o = 16; o; o >>= 1)
            lmax = fmaxf(lmax, __shfl_xor_sync(0xFFFFFFFFu, lmax, o));
        if (lane == 0)
            atomicMax((unsigned int*)&g_maxes[maxslot], __float_as_uint(lmax));
    }
}

// ---------------- launch -------------------------------------------------------
extern "C" void kernel_launch(void* const* d_in, const int* in_sizes, int n_in,
                              void* d_out, int out_size) {
    const float* x  = (const float*)d_in[0];
    const float* w1 = (const float*)d_in[1];
    const float* b1 = (const float*)d_in[2];
    const float* w2 = (const float*)d_in[3];
    const float* b2 = (const float*)d_in[4];
    const float* w3 = (const float*)d_in[5];
    const float* b3 = (const float*)d_in[6];
    float* out = (float*)d_out;

    void *p_xq, *p_w1q, *p_w2q, *p_w3q, *p_h, *p_hq, *p_part, *p_flags;
    cudaGetSymbolAddress(&p_xq, g_xq);
    cudaGetSymbolAddress(&p_w1q, g_w1q);
    cudaGetSymbolAddress(&p_w2q, g_w2q);
    cudaGetSymbolAddress(&p_w3q, g_w3q);
    cudaGetSymbolAddress(&p_h, g_h);
    cudaGetSymbolAddress(&p_hq, g_hq);
    cudaGetSymbolAddress(&p_part, g_part);
    cudaGetSymbolAddress(&p_flags, g_kflags);

    const int SMEM = STAGES * STAGE_BYTES;   // 98304
    cudaFuncSetAttribute(gemm_q_kernel,
                         cudaFuncAttributeMaxDynamicSharedMemorySize, SMEM);

    const int RB = 1184;  // 8 * 148 SMs, grid-stride

    cudaStream_t s1;
    cudaStreamCreateWithFlags(&s1, cudaStreamNonBlocking);
    cudaEvent_t e_w1m, e_aux;
    cudaEventCreateWithFlags(&e_w1m, cudaEventDisableTiming);
    cudaEventCreateWithFlags(&e_aux, cudaEventDisableTiming);

    init_maxes_kernel<<<1, 256>>>();

    // s0: w1 maxabs (needed by the chunk producer AND before GEMM1 launch path)
    maxabs_kernel<<<RB, 256>>>(w1, (4096 * 9216) / 4, 1);
    cudaEventRecord(e_w1m, 0);

    // s1 (forked): chunk-ordered w1 quant (producer, co-runs with GEMM1),
    // then w2/w3 aux hidden under GEMM1.
    cudaStreamWaitEvent(s1, e_w1m, 0);
    quant_w1_chunks_kernel<<<20, 256, 0, s1>>>(w1, (__nv_bfloat16*)p_w1q);
    maxabs_kernel<<<RB, 256, 0, s1>>>(w2, (4096 * 4096) / 4, 2);
    quant_kernel<<<RB, 256, 0, s1>>>(w2, (__nv_bfloat16*)p_w2q,
                                     (4096 * 4096) / 4, (4096 * 4096) / 4, 2,
                                     -127.0f);
    maxabs_kernel<<<RB, 256, 0, s1>>>(w3, (1000 * 4096) / 4, 3);
    quant_kernel<<<RB, 256, 0, s1>>>(w3, (__nv_bfloat16*)p_w3q,
                                     (1000 * 4096) / 4, (1024 * 4096) / 4, 3,
                                     -127.0f);
    cudaEventRecord(e_aux, s1);

    // s0: x aux (runs while producer warms up), then GEMM1 (spins on kflags)
    maxabs_kernel<<<RB, 256>>>(x, (512 * 9216) / 4, 0);
    quant_kernel<<<RB, 256>>>(x, (__nv_bfloat16*)p_xq,
                              (512 * 9216) / 4, (512 * 9216) / 4, 0, -128.0f);

    gemm_q_kernel<<<dim3(32, 4, 1), NTHREADS, SMEM>>>(
        (const __nv_bfloat16*)p_xq, (const __nv_bfloat16*)p_w1q, b1,
        (float*)p_h, (const unsigned*)p_flags,
        9216, 4096, 1, 4, 0, 1, 9216 / 64, 0, 4096);

    quant_kernel<<<RB, 256>>>((const float*)p_h, (__nv_bfloat16*)p_hq,
                              (512 * 4096) / 4, (512 * 4096) / 4, 4, -128.0f);

    // GEMM2 needs w2q (and downstream GEMM3 needs w3q)
    cudaStreamWaitEvent(0, e_aux, 0);
    gemm_q_kernel<<<dim3(32, 4, 1), NTHREADS, SMEM>>>(
        (const __nv_bfloat16*)p_hq, (const __nv_bfloat16*)p_w2q, b2,
        (float*)p_h, nullptr,
        4096, 4096, 1, 5, 4, 2, 4096 / 64, 0, 4096);
    quant_kernel<<<RB, 256>>>((const float*)p_h, (__nv_bfloat16*)p_hq,
                              (512 * 4096) / 4, (512 * 4096) / 4, 5, -128.0f);

    // Layer 3: split-K=4 raw partials (8x4x4 = 128 CTAs), then reduce
    gemm_q_kernel<<<dim3(8, 4, 4), NTHREADS, SMEM>>>(
        (const __nv_bfloat16*)p_hq, (const __nv_bfloat16*)p_w3q, b3,
        (float*)p_part, nullptr,
        4096, 1024, 0, -1, 5, 3, (4096 / 64) / 4, 1, 1024);
    reduce3_kernel<<<(512 * 500 + 255) / 256, 256>>>(b3, out);

    cudaEventDestroy(e_w1m);
    cudaEventDestroy(e_aux);
    cudaStreamDestroy(s1);
}

// round 13
// speedup vs baseline: 1.5550x; 1.5550x over previous
#include <cuda_runtime.h>
#include <cuda_bf16.h>
#include <cstdint>

#define NLV 127.0f

// ---------------- scratch (__device__ globals) -------------------------------
__device__ float g_maxes[8];                       // 0:x 1:w1 2:w2 3:w3 4:h1 5:h2
__device__ unsigned g_kflags[256];                 // per-K-chunk ready flags (w1q)
__device__ __nv_bfloat16 g_xq[512 * 9216];
__device__ __nv_bfloat16 g_w1q[4096 * 9216];
__device__ __nv_bfloat16 g_w2q[4096 * 4096];
__device__ __nv_bfloat16 g_w3q[1024 * 4096];       // padded 1000 -> 1024 rows
__device__ float g_h[512 * 4096];
__device__ __nv_bfloat16 g_hq[512 * 4096];
__device__ float g_part[4 * 512 * 1024];           // split-K partials for layer 3

// ---------------- helpers ----------------------------------------------------
__device__ __forceinline__ uint32_t smem_u32(const void* p) {
    uint32_t a;
    asm("{ .reg .u64 t; cvta.to.shared.u64 t, %1; cvt.u32.u64 %0, t; }"
        : "=r"(a) : "l"(p));
    return a;
}

__device__ __forceinline__ void cp_async16(uint32_t saddr, const void* g) {
    asm volatile("cp.async.cg.shared.global [%0], [%1], 16;"
                 :: "r"(saddr), "l"(g) : "memory");
}

#define CP_COMMIT() asm volatile("cp.async.commit_group;" ::: "memory")

__device__ __forceinline__ unsigned ld_acquire_gpu(const unsigned* p) {
    unsigned v;
    asm volatile("ld.acquire.gpu.u32 %0, [%1];" : "=r"(v) : "l"(p) : "memory");
    return v;
}

#define LDSM4(R, addr)                                                          \
    asm volatile("ldmatrix.sync.aligned.m8n8.x4.shared.b16 "                    \
                 "{%0, %1, %2, %3}, [%4];"                                      \
                 : "=r"((R)[0]), "=r"((R)[1]), "=r"((R)[2]), "=r"((R)[3])       \
                 : "r"(addr))

#define MMA16816(C, A, B0, B1)                                                  \
    asm volatile("mma.sync.aligned.m16n8k16.row.col.f32.bf16.bf16.f32 "         \
                 "{%0, %1, %2, %3}, {%4, %5, %6, %7}, {%8, %9}, "               \
                 "{%0, %1, %2, %3};"                                            \
                 : "+f"((C)[0]), "+f"((C)[1]), "+f"((C)[2]), "+f"((C)[3])       \
                 : "r"((A)[0]), "r"((A)[1]), "r"((A)[2]), "r"((A)[3]),          \
                   "r"(B0), "r"(B1))

// ---------------- small kernels ----------------------------------------------
__global__ void init_maxes_kernel() {
    if (threadIdx.x < 8) g_maxes[threadIdx.x] = 0.0f;
    if (threadIdx.x < 256) g_kflags[threadIdx.x] = 0u;
}

__global__ void maxabs_kernel(const float* __restrict__ src, int n4, int slot) {
    float m = 0.0f;
    const float4* s4 = (const float4*)src;
    for (int i = blockIdx.x * blockDim.x + threadIdx.x; i < n4;
         i += gridDim.x * blockDim.x) {
        float4 v = s4[i];
        m = fmaxf(m, fmaxf(fmaxf(fabsf(v.x), fabsf(v.y)),
                           fmaxf(fabsf(v.z), fabsf(v.w))));
    }
#pragma unroll
    for (int o = 16; o; o >>= 1) m = fmaxf(m, __shfl_xor_sync(0xFFFFFFFFu, m, o));
    __shared__ float sm[8];
    if ((threadIdx.x & 31) == 0) sm[threadIdx.x >> 5] = m;
    __syncthreads();
    if (threadIdx.x == 0) {
        float mm = sm[0];
#pragma unroll
        for (int w = 1; w < 8; w++) mm = fmaxf(mm, sm[w]);
        atomicMax((unsigned int*)&g_maxes[slot], __float_as_uint(mm));
    }
}

__device__ __forceinline__ uint32_t pack_bf16x2(float a, float b) {
    uint32_t lo = (uint32_t)__bfloat16_as_ushort(__float2bfloat16_rn(a));
    uint32_t hi = (uint32_t)__bfloat16_as_ushort(__float2bfloat16_rn(b));
    return lo | (hi << 16);
}

// quantize fp32 -> integer-valued bf16 (round-half-even, clip [lo,127])
__global__ void quant_kernel(const float* __restrict__ src,
                             __nv_bfloat16* __restrict__ dst,
                             int n4, int npad4, int slot, float lo) {
    float mx = g_maxes[slot];
    float scale = mx / NLV;
    if (!(scale > 0.0f)) scale = 1.0f;
    float inv = 1.0f / scale;
    for (int i = blockIdx.x * blockDim.x + threadIdx.x; i < npad4;
         i += gridDim.x * blockDim.x) {
        uint32_t w0 = 0u, w1 = 0u;
        if (i < n4) {
            float4 v = ((const float4*)src)[i];
            float q0 = fminf(fmaxf(rintf(v.x * inv), lo), NLV);
            float q1 = fminf(fmaxf(rintf(v.y * inv), lo), NLV);
            float q2 = fminf(fmaxf(rintf(v.z * inv), lo), NLV);
            float q3 = fminf(fmaxf(rintf(v.w * inv), lo), NLV);
            w0 = pack_bf16x2(q0, q1);
            w1 = pack_bf16x2(q2, q3);
        }
        ((uint2*)dst)[i] = make_uint2(w0, w1);
    }
}

// chunk-ordered w1 quantizer (producer for GEMM1). 48 CTAs x 512 threads.
// CTA b handles chunks b, b+48, b+96 (wavefront: low chunks complete first).
// Sets g_kflags[c] (release) when chunk c (64 cols) fully written.
__global__ void __launch_bounds__(512, 2)
quant_w1_chunks_kernel(const float* __restrict__ src,
                       __nv_bfloat16* __restrict__ dst) {
    float mx = g_maxes[1];
    float scale = mx / NLV;
    if (!(scale > 0.0f)) scale = 1.0f;
    float inv = 1.0f / scale;
    const int tid = threadIdx.x;
    const int q4 = tid & 15;        // float4 index within 64-col chunk-row
    const int r0 = tid >> 4;        // 0..31
    for (int c = blockIdx.x; c < 144; c += 48) {
#pragma unroll 4
        for (int it = 0; it < 128; it++) {
            int r = it * 32 + r0;
            size_t idx = (size_t)r * 2304 + c * 16 + q4;
            float4 v = ((const float4*)src)[idx];
            float a0 = fminf(fmaxf(rintf(v.x * inv), -NLV), NLV);
            float a1 = fminf(fmaxf(rintf(v.y * inv), -NLV), NLV);
            float a2 = fminf(fmaxf(rintf(v.z * inv), -NLV), NLV);
            float a3 = fminf(fmaxf(rintf(v.w * inv), -NLV), NLV);
            ((uint2*)dst)[idx] = make_uint2(pack_bf16x2(a0, a1),
                                            pack_bf16x2(a2, a3));
        }
        __threadfence();            // each thread's writes GPU-visible
        __syncthreads();            // all threads' fences done
        if (tid == 0)
            asm volatile("st.release.gpu.u32 [%0], %1;"
                         :: "l"(&g_kflags[c]), "r"(1u) : "memory");
    }
}

// split-K reduce for layer 3: sum 4 partials (fixed order), dequant + bias
__global__ void reduce3_kernel(const float* __restrict__ bias,
                               float* __restrict__ out) {
    int idx = blockIdx.x * blockDim.x + threadIdx.x;   // over 512*500 float2
    if (idx >= 512 * 500) return;
    int m = idx / 500;
    int n = (idx % 500) * 2;
    const float* p = g_part + m * 1024 + n;
    float s0 = 0.0f, s1 = 0.0f;
#pragma unroll
    for (int k = 0; k < 4; k++) {
        float2 v = *(const float2*)(p + k * (512 * 1024));
        s0 += v.x;
        s1 += v.y;
    }
    const float bs = (g_maxes[5] / NLV) * (g_maxes[3] / NLV);
    float o0 = s0 * bs + rintf(bias[n] / bs) * bs;
    float o1 = s1 * bs + rintf(bias[n + 1] / bs) * bs;
    *(float2*)(out + (size_t)m * 1000 + n) = make_float2(o0, o1);
}

// ---------------- HMMA GEMM ----------------------------------------------------
// C[M=512, Nout] = A[512,K] @ B[Npad,K]^T, bf16 in (integer-valued), fp32 accum.
// Tile 128x128x64, 3-stage cp.async pipeline, 8 warps (64x32 warp tiles).
// kflags != nullptr: spin (acquire) on per-K-chunk ready flag before prefetch.
constexpr int BM = 128, BN = 128, BK = 64, STAGES = 3, NTHREADS = 256;
constexpr int STAGE_BYTES = (BM * BK + BN * BK) * 2;   // 32768
constexpr int B_OFS = BM * BK * 2;                     // 16384

__global__ void __launch_bounds__(NTHREADS, 1)
gemm_q_kernel(const __nv_bfloat16* __restrict__ A,
              const __nv_bfloat16* __restrict__ B,
              const float* __restrict__ bias, float* __restrict__ out,
              const unsigned* kflags,
              int K, int Nout, int relu, int maxslot, int sa_slot, int sw_slot,
              int NK, int raw, int ostride) {
    extern __shared__ char smem_raw[];
    const uint32_t sb = smem_u32(smem_raw);

    const int tid = threadIdx.x;
    const int lane = tid & 31;
    const int wid = tid >> 5;
    const int wm = wid & 1;        // 2 m-blocks of 64
    const int wn = wid >> 1;       // 4 n-blocks of 32
    const int m0 = blockIdx.y * BM;
    const int n0 = blockIdx.x * BN;
    const size_t k_ofs = (size_t)blockIdx.z * NK * BK;
    float* outp = raw ? (out + (size_t)blockIdx.z * (512 * 1024)) : out;

    // ---- global->shared mapping: 2048 x 16B chunks / 256 threads = 8 each ----
    uint32_t s_st[8];
    const __nv_bfloat16* g_st[8];
#pragma unroll
    for (int i = 0; i < 8; i++) {
        int li = i * NTHREADS + tid;
        int isA = (li < 1024);
        int idx = li & 1023;
        int row = idx >> 3;            // 0..127
        int c = idx & 7;               // 16B chunk within 128B row
        s_st[i] = (uint32_t)((isA ? 0 : B_OFS) + row * 128 +
                             ((c ^ (row & 7)) << 4));
        g_st[i] = (isA ? (A + (size_t)(m0 + row) * K)
                       : (B + (size_t)(n0 + row) * K)) + k_ofs + c * 8;
    }

    // prologue loads
#pragma unroll
    for (int st = 0; st < 2; st++) {
        if (st < NK) {
            if (kflags) {
                if (tid == 0) while (ld_acquire_gpu(&kflags[st]) == 0) {}
                __syncthreads();
            }
            uint32_t base = sb + (uint32_t)(st % STAGES) * STAGE_BYTES;
#pragma unroll
            for (int i = 0; i < 8; i++)
                cp_async16(base + s_st[i], g_st[i] + (size_t)st * BK);
            CP_COMMIT();
        }
    }

    // ---- ldmatrix per-lane base addresses (within stage) ----
    const int r = lane & 7;
    const int g = lane >> 3;
    uint32_t a_row[4];
    int a_rx[4];
#pragma unroll
    for (int mi = 0; mi < 4; mi++) {
        int row = wm * 64 + mi * 16 + (g & 1) * 8 + r;
        a_row[mi] = (uint32_t)(row * 128);
        a_rx[mi] = row & 7;
    }
    uint32_t b_row[2];
    int b_rx[2];
#pragma unroll
    for (int p = 0; p < 2; p++) {
        int row = wn * 32 + p * 16 + (g >> 1) * 8 + r;
        b_row[p] = (uint32_t)(B_OFS + row * 128);
        b_rx[p] = row & 7;
    }

    float acc[4][4][4];
#pragma unroll
    for (int mi = 0; mi < 4; mi++)
#pragma unroll
        for (int ni = 0; ni < 4; ni++)
#pragma unroll
            for (int e = 0; e < 4; e++) acc[mi][ni][e] = 0.0f;

#pragma unroll 1
    for (int kc = 0; kc < NK; kc++) {
        if (kc + 2 < NK) {
            if (kflags) {
                if (tid == 0) while (ld_acquire_gpu(&kflags[kc + 2]) == 0) {}
                __syncthreads();
            }
            uint32_t base = sb + (uint32_t)((kc + 2) % STAGES) * STAGE_BYTES;
#pragma unroll
            for (int i = 0; i < 8; i++)
                cp_async16(base + s_st[i], g_st[i] + (size_t)(kc + 2) * BK);
            CP_COMMIT();
        }
        int rem = NK - 1 - kc;
        if (rem >= 2)      asm volatile("cp.async.wait_group 2;" ::: "memory");
        else if (rem == 1) asm volatile("cp.async.wait_group 1;" ::: "memory");
        else               asm volatile("cp.async.wait_group 0;" ::: "memory");
        __syncthreads();

        const uint32_t stage = sb + (uint32_t)(kc % STAGES) * STAGE_BYTES;
#pragma unroll
        for (int s = 0; s < 4; s++) {
            uint32_t af[4][4];
#pragma unroll
            for (int mi = 0; mi < 4; mi++) {
                int chunk = 2 * s + (g >> 1);
                LDSM4(af[mi], stage + a_row[mi] +
                              (uint32_t)((chunk ^ a_rx[mi]) << 4));
            }
            uint32_t bf[2][4];
#pragma unroll
            for (int p = 0; p < 2; p++) {
                int chunk = 2 * s + (g & 1);
                LDSM4(bf[p], stage + b_row[p] +
                             (uint32_t)((chunk ^ b_rx[p]) << 4));
            }
#pragma unroll
            for (int mi = 0; mi < 4; mi++) {
#pragma unroll
                for (int p = 0; p < 2; p++) {
                    MMA16816(acc[mi][2 * p],     af[mi], bf[p][0], bf[p][1]);
                    MMA16816(acc[mi][2 * p + 1], af[mi], bf[p][2], bf[p][3]);
                }
            }
        }
        __syncthreads();
    }

    // ---- epilogue ----
    if (raw) {
#pragma unroll
        for (int mi = 0; mi < 4; mi++) {
#pragma unroll
            for (int half = 0; half < 2; half++) {
                int m = m0 + wm * 64 + mi * 16 + (lane >> 2) + half * 8;
#pragma unroll
                for (int ni = 0; ni < 4; ni++) {
                    int n = n0 + wn * 32 + ni * 8 + (lane & 3) * 2;
                    *(float2*)(outp + (size_t)m * ostride + n) =
                        make_float2(acc[mi][ni][half * 2 + 0],
                                    acc[mi][ni][half * 2 + 1]);
                }
            }
        }
        return;
    }

    const float sa = g_maxes[sa_slot] / NLV;
    const float sw = g_maxes[sw_slot] / NLV;
    const float bs = sa * sw;
    float lmax = 0.0f;

    float bq[4][2];
#pragma unroll
    for (int ni = 0; ni < 4; ni++) {
        int n = n0 + wn * 32 + ni * 8 + (lane & 3) * 2;
#pragma unroll
        for (int e = 0; e < 2; e++)
            bq[ni][e] = (n + e < Nout) ? rintf(bias[n + e] / bs) * bs : 0.0f;
    }

#pragma unroll
    for (int mi = 0; mi < 4; mi++) {
#pragma unroll
        for (int half = 0; half < 2; half++) {
            int m = m0 + wm * 64 + mi * 16 + (lane >> 2) + half * 8;
#pragma unroll
            for (int ni = 0; ni < 4; ni++) {
                int n = n0 + wn * 32 + ni * 8 + (lane & 3) * 2;
                if (n < Nout) {
                    float v0 = acc[mi][ni][half * 2 + 0] * bs + bq[ni][0];
                    float v1 = acc[mi][ni][half * 2 + 1] * bs + bq[ni][1];
                    if (relu) { v0 = fmaxf(v0, 0.0f); v1 = fmaxf(v1, 0.0f); }
                    *(float2*)(outp + (size_t)m * ostride + n) =
                        make_float2(v0, v1);
                    lmax = fmaxf(lmax, fmaxf(fabsf(v0), fabsf(v1)));
                }
            }
        }
    }
    if (maxslot >= 0) {
#pragma unroll
        for (int o = 16; o; o >>= 1)
            lmax = fmaxf(lmax, __shfl_xor_sync(0xFFFFFFFFu, lmax, o));
        if (lane == 0)
            atomicMax((unsigned int*)&g_maxes[maxslot], __float_as_uint(lmax));
    }
}

// ---------------- launch -------------------------------------------------------
extern "C" void kernel_launch(void* const* d_in, const int* in_sizes, int n_in,
                              void* d_out, int out_size) {
    const float* x  = (const float*)d_in[0];
    const float* w1 = (const float*)d_in[1];
    const float* b1 = (const float*)d_in[2];
    const float* w2 = (const float*)d_in[3];
    const float* b2 = (const float*)d_in[4];
    const float* w3 = (const float*)d_in[5];
    const float* b3 = (const float*)d_in[6];
    float* out = (float*)d_out;

    void *p_xq, *p_w1q, *p_w2q, *p_w3q, *p_h, *p_hq, *p_part, *p_flags;
    cudaGetSymbolAddress(&p_xq, g_xq);
    cudaGetSymbolAddress(&p_w1q, g_w1q);
    cudaGetSymbolAddress(&p_w2q, g_w2q);
    cudaGetSymbolAddress(&p_w3q, g_w3q);
    cudaGetSymbolAddress(&p_h, g_h);
    cudaGetSymbolAddress(&p_hq, g_hq);
    cudaGetSymbolAddress(&p_part, g_part);
    cudaGetSymbolAddress(&p_flags, g_kflags);

    const int SMEM = STAGES * STAGE_BYTES;   // 98304
    cudaFuncSetAttribute(gemm_q_kernel,
                         cudaFuncAttributeMaxDynamicSharedMemorySize, SMEM);

    const int RB = 1184;  // 8 * 148 SMs, grid-stride

    cudaStream_t s1, s2;
    cudaStreamCreateWithFlags(&s1, cudaStreamNonBlocking);
    cudaStreamCreateWithFlags(&s2, cudaStreamNonBlocking);
    cudaEvent_t e_init, e_w1m, e_x, e_aux;
    cudaEventCreateWithFlags(&e_init, cudaEventDisableTiming);
    cudaEventCreateWithFlags(&e_w1m, cudaEventDisableTiming);
    cudaEventCreateWithFlags(&e_x, cudaEventDisableTiming);
    cudaEventCreateWithFlags(&e_aux, cudaEventDisableTiming);

    init_maxes_kernel<<<1, 256>>>();
    cudaEventRecord(e_init, 0);

    // s0: w1 maxabs (prerequisite for the producer)
    maxabs_kernel<<<RB, 256>>>(w1, (4096 * 9216) / 4, 1);
    cudaEventRecord(e_w1m, 0);

    // s1: x aux concurrent with w1 maxabs
    cudaStreamWaitEvent(s1, e_init, 0);
    maxabs_kernel<<<RB, 256, 0, s1>>>(x, (512 * 9216) / 4, 0);
    quant_kernel<<<RB, 256, 0, s1>>>(x, (__nv_bfloat16*)p_xq,
                                     (512 * 9216) / 4, (512 * 9216) / 4, 0,
                                     -128.0f);
    cudaEventRecord(e_x, s1);

    // s2: wavefront w1 quant producer (48 CTAs), then w2/w3 aux under GEMM1
    cudaStreamWaitEvent(s2, e_w1m, 0);
    quant_w1_chunks_kernel<<<48, 512, 0, s2>>>(w1, (__nv_bfloat16*)p_w1q);
    maxabs_kernel<<<RB, 256, 0, s2>>>(w2, (4096 * 4096) / 4, 2);
    quant_kernel<<<RB, 256, 0, s2>>>(w2, (__nv_bfloat16*)p_w2q,
                                     (4096 * 4096) / 4, (4096 * 4096) / 4, 2,
                                     -127.0f);
    maxabs_kernel<<<RB, 256, 0, s2>>>(w3, (1000 * 4096) / 4, 3);
    quant_kernel<<<RB, 256, 0, s2>>>(w3, (__nv_bfloat16*)p_w3q,
                                     (1000 * 4096) / 4, (1024 * 4096) / 4, 3,
                                     -127.0f);
    cudaEventRecord(e_aux, s2);

    // s0: GEMM1 (spins on per-chunk flags fed by the producer)
    cudaStreamWaitEvent(0, e_x, 0);
    gemm_q_kernel<<<dim3(32, 4, 1), NTHREADS, SMEM>>>(
        (const __nv_bfloat16*)p_xq, (const __nv_bfloat16*)p_w1q, b1,
        (float*)p_h, (const unsigned*)p_flags,
        9216, 4096, 1, 4, 0, 1, 9216 / 64, 0, 4096);

    quant_kernel<<<RB, 256>>>((const float*)p_h, (__nv_bfloat16*)p_hq,
                              (512 * 4096) / 4, (512 * 4096) / 4, 4, -128.0f);

    // GEMM2 needs w2q (and downstream GEMM3 needs w3q)
    cudaStreamWaitEvent(0, e_aux, 0);
    gemm_q_kernel<<<dim3(32, 4, 1), NTHREADS, SMEM>>>(
        (const __nv_bfloat16*)p_hq, (const __nv_bfloat16*)p_w2q, b2,
        (float*)p_h, nullptr,
        4096, 4096, 1, 5, 4, 2, 4096 / 64, 0, 4096);
    quant_kernel<<<RB, 256>>>((const float*)p_h, (__nv_bfloat16*)p_hq,
                              (512 * 4096) / 4, (512 * 4096) / 4, 5, -128.0f);

    // Layer 3: split-K=4 raw partials (8x4x4 = 128 CTAs), then reduce
    gemm_q_kernel<<<dim3(8, 4, 4), NTHREADS, SMEM>>>(
        (const __nv_bfloat16*)p_hq, (const __nv_bfloat16*)p_w3q, b3,
        (float*)p_part, nullptr,
        4096, 1024, 0, -1, 5, 3, (4096 / 64) / 4, 1, 1024);
    reduce3_kernel<<<(512 * 500 + 255) / 256, 256>>>(b3, out);

    cudaEventDestroy(e_init);
    cudaEventDestroy(e_w1m);
    cudaEventDestroy(e_x);
    cudaEventDestroy(e_aux);
    cudaStreamDestroy(s1);
    cudaStreamDestroy(s2);
}

// round 14
// speedup vs baseline: 1.8565x; 1.1938x over previous
#include <cuda_runtime.h>
#include <cuda_bf16.h>
#include <cstdint>

#define NLV 127.0f

// ---------------- scratch (__device__ globals) -------------------------------
__device__ float g_maxes[8];                       // 0:x 1:w1 2:w2 3:w3 4:h1 5:h2
__device__ __nv_bfloat16 g_xq[512 * 9216];
__device__ __nv_bfloat16 g_w1q[4096 * 9216];
__device__ __nv_bfloat16 g_w2q[4096 * 4096];
__device__ __nv_bfloat16 g_w3q[1024 * 4096];       // padded 1000 -> 1024 rows
__device__ float g_h[512 * 4096];                  // GEMM1 out
__device__ float g_h2[512 * 4096];                 // GEMM2 out
__device__ float g_part[4 * 512 * 1024];           // split-K partials for layer 3

// ---------------- helpers ----------------------------------------------------
__device__ __forceinline__ uint32_t smem_u32(const void* p) {
    uint32_t a;
    asm("{ .reg .u64 t; cvta.to.shared.u64 t, %1; cvt.u32.u64 %0, t; }"
        : "=r"(a) : "l"(p));
    return a;
}

__device__ __forceinline__ void cp_async16(uint32_t saddr, const void* g) {
    asm volatile("cp.async.cg.shared.global [%0], [%1], 16;"
                 :: "r"(saddr), "l"(g) : "memory");
}

#define CP_COMMIT() asm volatile("cp.async.commit_group;" ::: "memory")

#define LDSM4(R, addr)                                                          \
    asm volatile("ldmatrix.sync.aligned.m8n8.x4.shared.b16 "                    \
                 "{%0, %1, %2, %3}, [%4];"                                      \
                 : "=r"((R)[0]), "=r"((R)[1]), "=r"((R)[2]), "=r"((R)[3])       \
                 : "r"(addr))

#define MMA16816(C, A, B0, B1)                                                  \
    asm volatile("mma.sync.aligned.m16n8k16.row.col.f32.bf16.bf16.f32 "         \
                 "{%0, %1, %2, %3}, {%4, %5, %6, %7}, {%8, %9}, "               \
                 "{%0, %1, %2, %3};"                                            \
                 : "+f"((C)[0]), "+f"((C)[1]), "+f"((C)[2]), "+f"((C)[3])       \
                 : "r"((A)[0]), "r"((A)[1]), "r"((A)[2]), "r"((A)[3]),          \
                   "r"(B0), "r"(B1))

__device__ __forceinline__ uint32_t pack_bf16x2(float a, float b) {
    uint32_t lo = (uint32_t)__bfloat16_as_ushort(__float2bfloat16_rn(a));
    uint32_t hi = (uint32_t)__bfloat16_as_ushort(__float2bfloat16_rn(b));
    return lo | (hi << 16);
}

// ---------------- small kernels ----------------------------------------------
__global__ void init_maxes_kernel() {
    if (threadIdx.x < 8) g_maxes[threadIdx.x] = 0.0f;
}

__global__ void maxabs_kernel(const float* __restrict__ src, int n4, int slot) {
    float m = 0.0f;
    const float4* s4 = (const float4*)src;
    for (int i = blockIdx.x * blockDim.x + threadIdx.x; i < n4;
         i += gridDim.x * blockDim.x) {
        float4 v = s4[i];
        m = fmaxf(m, fmaxf(fmaxf(fabsf(v.x), fabsf(v.y)),
                           fmaxf(fabsf(v.z), fabsf(v.w))));
    }
#pragma unroll
    for (int o = 16; o; o >>= 1) m = fmaxf(m, __shfl_xor_sync(0xFFFFFFFFu, m, o));
    __shared__ float sm[8];
    if ((threadIdx.x & 31) == 0) sm[threadIdx.x >> 5] = m;
    __syncthreads();
    if (threadIdx.x == 0) {
        float mm = sm[0];
#pragma unroll
        for (int w = 1; w < 8; w++) mm = fmaxf(mm, sm[w]);
        atomicMax((unsigned int*)&g_maxes[slot], __float_as_uint(mm));
    }
}

// quantize fp32 -> integer-valued bf16 (round-half-even, clip [lo,127])
__global__ void quant_kernel(const float* __restrict__ src,
                             __nv_bfloat16* __restrict__ dst,
                             int n4, int npad4, int slot, float lo) {
    float mx = g_maxes[slot];
    float scale = mx / NLV;
    if (!(scale > 0.0f)) scale = 1.0f;
    float inv = 1.0f / scale;
    for (int i = blockIdx.x * blockDim.x + threadIdx.x; i < npad4;
         i += gridDim.x * blockDim.x) {
        uint32_t w0 = 0u, w1 = 0u;
        if (i < n4) {
            float4 v = ((const float4*)src)[i];
            float q0 = fminf(fmaxf(rintf(v.x * inv), lo), NLV);
            float q1 = fminf(fmaxf(rintf(v.y * inv), lo), NLV);
            float q2 = fminf(fmaxf(rintf(v.z * inv), lo), NLV);
            float q3 = fminf(fmaxf(rintf(v.w * inv), lo), NLV);
            w0 = pack_bf16x2(q0, q1);
            w1 = pack_bf16x2(q2, q3);
        }
        ((uint2*)dst)[i] = make_uint2(w0, w1);
    }
}

// split-K reduce for layer 3: sum 4 partials (fixed order), dequant + bias
__global__ void reduce3_kernel(const float* __restrict__ bias,
                               float* __restrict__ out) {
    int idx = blockIdx.x * blockDim.x + threadIdx.x;   // over 512*500 float2
    if (idx >= 512 * 500) return;
    int m = idx / 500;
    int n = (idx % 500) * 2;
    const float* p = g_part + m * 1024 + n;
    float s0 = 0.0f, s1 = 0.0f;
#pragma unroll
    for (int k = 0; k < 4; k++) {
        float2 v = *(const float2*)(p + k * (512 * 1024));
        s0 += v.x;
        s1 += v.y;
    }
    const float bs = (g_maxes[5] / NLV) * (g_maxes[3] / NLV);
    float o0 = s0 * bs + rintf(bias[n] / bs) * bs;
    float o1 = s1 * bs + rintf(bias[n + 1] / bs) * bs;
    *(float2*)(out + (size_t)m * 1000 + n) = make_float2(o0, o1);
}

// ---------------- HMMA GEMM ----------------------------------------------------
// C[M=512, Nout] = A[512,K] @ B[Npad,K]^T, fp32 accum.
// AQ=0: A is pre-quantized bf16, loaded via cp.async (3-stage with B).
// AQ=1: A is fp32 (L2-resident); quantized in-register in the producer
//       (scale g_maxes[sa_slot]/127, identical math to quant_kernel),
//       double-buffered SMEM; B stays on the 3-stage cp.async pipeline.
// Tile 128x128x64, 8 warps (64x32 warp tiles).
constexpr int BM = 128, BN = 128, BK = 64, NTHREADS = 256;
constexpr int TILE_B = BM * BK * 2;                 // 16384 per A/B tile
constexpr int B_SM = 3 * TILE_B;                    // B region at 49152
constexpr int SMEM_TOTAL = B_SM + 3 * TILE_B;       // 98304

template <int AQ>
__global__ void __launch_bounds__(NTHREADS, 1)
gemm_q_kernel(const __nv_bfloat16* __restrict__ A,
              const float* __restrict__ Afp,
              const __nv_bfloat16* __restrict__ B,
              const float* __restrict__ bias, float* __restrict__ out,
              int K, int Nout, int relu, int maxslot, int sa_slot, int sw_slot,
              int NK, int raw, int ostride) {
    extern __shared__ char smem_raw[];
    const uint32_t sb = smem_u32(smem_raw);

    const int tid = threadIdx.x;
    const int lane = tid & 31;
    const int wid = tid >> 5;
    const int wm = wid & 1;        // 2 m-blocks of 64
    const int wn = wid >> 1;       // 4 n-blocks of 32
    const int m0 = blockIdx.y * BM;
    const int n0 = blockIdx.x * BN;
    const size_t k_ofs = (size_t)blockIdx.z * NK * BK;
    float* outp = raw ? (out + (size_t)blockIdx.z * (512 * 1024)) : out;

    const float sa = g_maxes[sa_slot] / NLV;
    const float sw = g_maxes[sw_slot] / NLV;
    float inva = 1.0f / ((sa > 0.0f) ? sa : 1.0f);

    // ---- per-thread tile mappings: 1024 chunks each for A and B, 4/thread ----
    uint32_t a_st[4], b_st[4];
    const __nv_bfloat16* a_g[4];
    const float* a_gf[4];
    const __nv_bfloat16* b_g[4];
#pragma unroll
    for (int i = 0; i < 4; i++) {
        int li = i * NTHREADS + tid;
        int row = li >> 3;
        int c = li & 7;
        uint32_t sw_off = (uint32_t)(row * 128 + ((c ^ (row & 7)) << 4));
        a_st[i] = sw_off;
        b_st[i] = (uint32_t)B_SM + sw_off;
        if (AQ) a_gf[i] = Afp + (size_t)(m0 + row) * K + k_ofs + c * 8;
        else    a_g[i]  = A   + (size_t)(m0 + row) * K + k_ofs + c * 8;
        b_g[i] = B + (size_t)(n0 + row) * K + k_ofs + c * 8;
    }

    float4 va[8];   // staged fp32 A data (AQ=1)

#define LDGA(kc_)                                                               \
    do {                                                                        \
        _Pragma("unroll")                                                       \
        for (int i = 0; i < 4; i++) {                                           \
            va[2 * i]     = *(const float4*)(a_gf[i] + (size_t)(kc_) * BK);     \
            va[2 * i + 1] = *(const float4*)(a_gf[i] + (size_t)(kc_) * BK + 4); \
        }                                                                       \
    } while (0)

#define CVT_STS_A(buf_)                                                         \
    do {                                                                        \
        _Pragma("unroll")                                                       \
        for (int i = 0; i < 4; i++) {                                           \
            float f[8] = {va[2*i].x, va[2*i].y, va[2*i].z, va[2*i].w,           \
                          va[2*i+1].x, va[2*i+1].y, va[2*i+1].z, va[2*i+1].w};  \
            _Pragma("unroll")                                                   \
            for (int j = 0; j < 8; j++)                                         \
                f[j] = fminf(fmaxf(rintf(f[j] * inva), -128.0f), NLV);          \
            uint32_t p0 = pack_bf16x2(f[0], f[1]);                              \
            uint32_t p1 = pack_bf16x2(f[2], f[3]);                              \
            uint32_t p2 = pack_bf16x2(f[4], f[5]);                              \
            uint32_t p3 = pack_bf16x2(f[6], f[7]);                              \
            asm volatile("st.shared.v4.b32 [%0], {%1, %2, %3, %4};"             \
                         :: "r"(sb + a_st[i] + (uint32_t)(buf_) * TILE_B),      \
                            "r"(p0), "r"(p1), "r"(p2), "r"(p3) : "memory");     \
        }                                                                       \
    } while (0)

    // ---- prologue ----
    if (AQ) {
        LDGA(0);
#pragma unroll
        for (int st = 0; st < 2; st++) {
            if (st < NK) {
#pragma unroll
                for (int i = 0; i < 4; i++)
                    cp_async16(sb + b_st[i] + (uint32_t)(st % 3) * TILE_B,
                               b_g[i] + (size_t)st * BK);
                CP_COMMIT();
            }
        }
        CVT_STS_A(0);
        if (NK > 1) LDGA(1);
    } else {
#pragma unroll
        for (int st = 0; st < 2; st++) {
            if (st < NK) {
#pragma unroll
                for (int i = 0; i < 4; i++)
                    cp_async16(sb + a_st[i] + (uint32_t)(st % 3) * TILE_B,
                               a_g[i] + (size_t)st * BK);
#pragma unroll
                for (int i = 0; i < 4; i++)
                    cp_async16(sb + b_st[i] + (uint32_t)(st % 3) * TILE_B,
                               b_g[i] + (size_t)st * BK);
                CP_COMMIT();
            }
        }
    }

    // ---- ldmatrix per-lane base addresses ----
    const int r = lane & 7;
    const int g = lane >> 3;
    uint32_t a_row[4];
    int a_rx[4];
#pragma unroll
    for (int mi = 0; mi < 4; mi++) {
        int row = wm * 64 + mi * 16 + (g & 1) * 8 + r;
        a_row[mi] = (uint32_t)(row * 128);
        a_rx[mi] = row & 7;
    }
    uint32_t b_row[2];
    int b_rx[2];
#pragma unroll
    for (int p = 0; p < 2; p++) {
        int row = wn * 32 + p * 16 + (g >> 1) * 8 + r;
        b_row[p] = (uint32_t)(B_SM + row * 128);
        b_rx[p] = row & 7;
    }

    float acc[4][4][4];
#pragma unroll
    for (int mi = 0; mi < 4; mi++)
#pragma unroll
        for (int ni = 0; ni < 4; ni++)
#pragma unroll
            for (int e = 0; e < 4; e++) acc[mi][ni][e] = 0.0f;

#pragma unroll 1
    for (int kc = 0; kc < NK; kc++) {
        if (kc + 2 < NK) {
            if (!AQ) {
#pragma unroll
                for (int i = 0; i < 4; i++)
                    cp_async16(sb + a_st[i] + (uint32_t)((kc + 2) % 3) * TILE_B,
                               a_g[i] + (size_t)(kc + 2) * BK);
            }
#pragma unroll
            for (int i = 0; i < 4; i++)
                cp_async16(sb + b_st[i] + (uint32_t)((kc + 2) % 3) * TILE_B,
                           b_g[i] + (size_t)(kc + 2) * BK);
            CP_COMMIT();
        }
        int rem = NK - 1 - kc;
        if (rem >= 2)      asm volatile("cp.async.wait_group 2;" ::: "memory");
        else if (rem == 1) asm volatile("cp.async.wait_group 1;" ::: "memory");
        else               asm volatile("cp.async.wait_group 0;" ::: "memory");
        __syncthreads();

        const uint32_t stageA = AQ ? (uint32_t)(kc & 1) * TILE_B
                                   : (uint32_t)(kc % 3) * TILE_B;
        const uint32_t stageB = (uint32_t)(kc % 3) * TILE_B;
#pragma unroll
        for (int s = 0; s < 4; s++) {
            uint32_t af[4][4];
#pragma unroll
            for (int mi = 0; mi < 4; mi++) {
                int chunk = 2 * s + (g >> 1);
                LDSM4(af[mi], sb + stageA + a_row[mi] +
                              (uint32_t)((chunk ^ a_rx[mi]) << 4));
            }
            uint32_t bf[2][4];
#pragma unroll
            for (int p = 0; p < 2; p++) {
                int chunk = 2 * s + (g & 1);
                LDSM4(bf[p], sb + stageB + b_row[p] +
                             (uint32_t)((chunk ^ b_rx[p]) << 4));
            }
#pragma unroll
            for (int mi = 0; mi < 4; mi++) {
#pragma unroll
                for (int p = 0; p < 2; p++) {
                    MMA16816(acc[mi][2 * p],     af[mi], bf[p][0], bf[p][1]);
                    MMA16816(acc[mi][2 * p + 1], af[mi], bf[p][2], bf[p][3]);
                }
            }
        }

        if (AQ && kc + 1 < NK) {
            CVT_STS_A((kc + 1) & 1);
            if (kc + 2 < NK) LDGA(kc + 2);
        }
        __syncthreads();
    }

    // ---- epilogue ----
    if (raw) {
#pragma unroll
        for (int mi = 0; mi < 4; mi++) {
#pragma unroll
            for (int half = 0; half < 2; half++) {
                int m = m0 + wm * 64 + mi * 16 + (lane >> 2) + half * 8;
#pragma unroll
                for (int ni = 0; ni < 4; ni++) {
                    int n = n0 + wn * 32 + ni * 8 + (lane & 3) * 2;
                    *(float2*)(outp + (size_t)m * ostride + n) =
                        make_float2(acc[mi][ni][half * 2 + 0],
                                    acc[mi][ni][half * 2 + 1]);
                }
            }
        }
        return;
    }

    const float bs = sa * sw;
    float lmax = 0.0f;

    float bq[4][2];
#pragma unroll
    for (int ni = 0; ni < 4; ni++) {
        int n = n0 + wn * 32 + ni * 8 + (lane & 3) * 2;
#pragma unroll
        for (int e = 0; e < 2; e++)
            bq[ni][e] = (n + e < Nout) ? rintf(bias[n + e] / bs) * bs : 0.0f;
    }

#pragma unroll
    for (int mi = 0; mi < 4; mi++) {
#pragma unroll
        for (int half = 0; half < 2; half++) {
            int m = m0 + wm * 64 + mi * 16 + (lane >> 2) + half * 8;
#pragma unroll
            for (int ni = 0; ni < 4; ni++) {
                int n = n0 + wn * 32 + ni * 8 + (lane & 3) * 2;
                if (n < Nout) {
                    float v0 = acc[mi][ni][half * 2 + 0] * bs + bq[ni][0];
                    float v1 = acc[mi][ni][half * 2 + 1] * bs + bq[ni][1];
                    if (relu) { v0 = fmaxf(v0, 0.0f); v1 = fmaxf(v1, 0.0f); }
                    *(float2*)(outp + (size_t)m * ostride + n) =
                        make_float2(v0, v1);
                    lmax = fmaxf(lmax, fmaxf(fabsf(v0), fabsf(v1)));
                }
            }
        }
    }
    if (maxslot >= 0) {
#pragma unroll
        for (int o = 16; o; o >>= 1)
            lmax = fmaxf(lmax, __shfl_xor_sync(0xFFFFFFFFu, lmax, o));
        if (lane == 0)
            atomicMax((unsigned int*)&g_maxes[maxslot], __float_as_uint(lmax));
    }
}

// ---------------- launch -------------------------------------------------------
extern "C" void kernel_launch(void* const* d_in, const int* in_sizes, int n_in,
                              void* d_out, int out_size) {
    const float* x  = (const float*)d_in[0];
    const float* w1 = (const float*)d_in[1];
    const float* b1 = (const float*)d_in[2];
    const float* w2 = (const float*)d_in[3];
    const float* b2 = (const float*)d_in[4];
    const float* w3 = (const float*)d_in[5];
    const float* b3 = (const float*)d_in[6];
    float* out = (float*)d_out;

    void *p_xq, *p_w1q, *p_w2q, *p_w3q, *p_h, *p_h2, *p_part;
    cudaGetSymbolAddress(&p_xq, g_xq);
    cudaGetSymbolAddress(&p_w1q, g_w1q);
    cudaGetSymbolAddress(&p_w2q, g_w2q);
    cudaGetSymbolAddress(&p_w3q, g_w3q);
    cudaGetSymbolAddress(&p_h, g_h);
    cudaGetSymbolAddress(&p_h2, g_h2);
    cudaGetSymbolAddress(&p_part, g_part);

    cudaFuncSetAttribute(gemm_q_kernel<0>,
                         cudaFuncAttributeMaxDynamicSharedMemorySize, SMEM_TOTAL);
    cudaFuncSetAttribute(gemm_q_kernel<1>,
                         cudaFuncAttributeMaxDynamicSharedMemorySize, SMEM_TOTAL);

    const int RB = 1184;  // 8 * 148 SMs, grid-stride

    cudaStream_t s1;
    cudaStreamCreateWithFlags(&s1, cudaStreamNonBlocking);
    cudaEvent_t e_init, e_x, e_w1, e_aux;
    cudaEventCreateWithFlags(&e_init, cudaEventDisableTiming);
    cudaEventCreateWithFlags(&e_x, cudaEventDisableTiming);
    cudaEventCreateWithFlags(&e_w1, cudaEventDisableTiming);
    cudaEventCreateWithFlags(&e_aux, cudaEventDisableTiming);

    init_maxes_kernel<<<1, 32>>>();
    cudaEventRecord(e_init, 0);

    // s0 critical path: w1 aux
    maxabs_kernel<<<RB, 256>>>(w1, (4096 * 9216) / 4, 1);
    quant_kernel<<<RB, 256>>>(w1, (__nv_bfloat16*)p_w1q,
                              (4096 * 9216) / 4, (4096 * 9216) / 4, 1, -127.0f);
    cudaEventRecord(e_w1, 0);

    // s1: x aux concurrent with w1 aux
    cudaStreamWaitEvent(s1, e_init, 0);
    maxabs_kernel<<<RB, 256, 0, s1>>>(x, (512 * 9216) / 4, 0);
    quant_kernel<<<RB, 256, 0, s1>>>(x, (__nv_bfloat16*)p_xq,
                                     (512 * 9216) / 4, (512 * 9216) / 4, 0,
                                     -128.0f);
    cudaEventRecord(e_x, s1);

    // GEMM1 (A = pre-quantized xq, bf16 path)
    cudaStreamWaitEvent(0, e_x, 0);
    gemm_q_kernel<0><<<dim3(32, 4, 1), NTHREADS, SMEM_TOTAL>>>(
        (const __nv_bfloat16*)p_xq, nullptr, (const __nv_bfloat16*)p_w1q, b1,
        (float*)p_h, 9216, 4096, 1, 4, 0, 1, 9216 / 64, 0, 4096);

    // s1: w2/w3 aux under GEMM1
    cudaStreamWaitEvent(s1, e_w1, 0);
    maxabs_kernel<<<RB, 256, 0, s1>>>(w2, (4096 * 4096) / 4, 2);
    quant_kernel<<<RB, 256, 0, s1>>>(w2, (__nv_bfloat16*)p_w2q,
                                     (4096 * 4096) / 4, (4096 * 4096) / 4, 2,
                                     -127.0f);
    maxabs_kernel<<<RB, 256, 0, s1>>>(w3, (1000 * 4096) / 4, 3);
    quant_kernel<<<RB, 256, 0, s1>>>(w3, (__nv_bfloat16*)p_w3q,
                                     (1000 * 4096) / 4, (1024 * 4096) / 4, 3,
                                     -127.0f);
    cudaEventRecord(e_aux, s1);

    // GEMM2: A = h (fp32, L2-resident), quantized in-producer with slot-4 scale
    cudaStreamWaitEvent(0, e_aux, 0);
    gemm_q_kernel<1><<<dim3(32, 4, 1), NTHREADS, SMEM_TOTAL>>>(
        nullptr, (const float*)p_h, (const __nv_bfloat16*)p_w2q, b2,
        (float*)p_h2, 4096, 4096, 1, 5, 4, 2, 4096 / 64, 0, 4096);

    // GEMM3: A = h2 (fp32), split-K=4 raw partials (8x4x4 = 128 CTAs), reduce
    gemm_q_kernel<1><<<dim3(8, 4, 4), NTHREADS, SMEM_TOTAL>>>(
        nullptr, (const float*)p_h2, (const __nv_bfloat16*)p_w3q, b3,
        (float*)p_part, 4096, 1024, 0, -1, 5, 3, (4096 / 64) / 4, 1, 1024);
    reduce3_kernel<<<(512 * 500 + 255) / 256, 256>>>(b3, out);

    cudaEventDestroy(e_init);
    cudaEventDestroy(e_x);
    cudaEventDestroy(e_w1);
    cudaEventDestroy(e_aux);
    cudaStreamDestroy(s1);
}

// round 15
// speedup vs baseline: 2.1402x; 1.1528x over previous
#include <cuda_runtime.h>
#include <cuda_bf16.h>
#include <cstdint>

#define NLV 127.0f

// ---------------- scratch (__device__ globals) -------------------------------
__device__ float g_maxes[8];                       // 0:x 1:w1 2:w2 3:w3 4:h1 5:h2
__device__ __nv_bfloat16 g_xq[512 * 9216];
__device__ __nv_bfloat16 g_w1q[4096 * 9216];
__device__ __nv_bfloat16 g_w2q[4096 * 4096];
__device__ __nv_bfloat16 g_w3q[1024 * 4096];       // padded 1000 -> 1024 rows
__device__ float g_h[512 * 4096];
__device__ __nv_bfloat16 g_hq[512 * 4096];
__device__ float g_part[4 * 512 * 1024];           // split-K partials for layer 3

// ---------------- helpers ----------------------------------------------------
__device__ __forceinline__ uint32_t smem_u32(const void* p) {
    uint32_t a;
    asm("{ .reg .u64 t; cvta.to.shared.u64 t, %1; cvt.u32.u64 %0, t; }"
        : "=r"(a) : "l"(p));
    return a;
}

__device__ __forceinline__ void cp_async16(uint32_t saddr, const void* g) {
    asm volatile("cp.async.cg.shared.global [%0], [%1], 16;"
                 :: "r"(saddr), "l"(g) : "memory");
}

#define CP_COMMIT() asm volatile("cp.async.commit_group;" ::: "memory")

#define LDSM4(R, addr)                                                          \
    asm volatile("ldmatrix.sync.aligned.m8n8.x4.shared.b16 "                    \
                 "{%0, %1, %2, %3}, [%4];"                                      \
                 : "=r"((R)[0]), "=r"((R)[1]), "=r"((R)[2]), "=r"((R)[3])       \
                 : "r"(addr))

#define MMA16816(C, A, B0, B1)                                                  \
    asm volatile("mma.sync.aligned.m16n8k16.row.col.f32.bf16.bf16.f32 "         \
                 "{%0, %1, %2, %3}, {%4, %5, %6, %7}, {%8, %9}, "               \
                 "{%0, %1, %2, %3};"                                            \
                 : "+f"((C)[0]), "+f"((C)[1]), "+f"((C)[2]), "+f"((C)[3])       \
                 : "r"((A)[0]), "r"((A)[1]), "r"((A)[2]), "r"((A)[3]),          \
                   "r"(B0), "r"(B1))

// ---------------- small kernels ----------------------------------------------
__global__ void init_maxes_kernel() {
    if (threadIdx.x < 8) g_maxes[threadIdx.x] = 0.0f;
}

__global__ void maxabs_kernel(const float* __restrict__ src, int n4, int slot) {
    float m = 0.0f;
    const float4* s4 = (const float4*)src;
    for (int i = blockIdx.x * blockDim.x + threadIdx.x; i < n4;
         i += gridDim.x * blockDim.x) {
        float4 v = s4[i];
        m = fmaxf(m, fmaxf(fmaxf(fabsf(v.x), fabsf(v.y)),
                           fmaxf(fabsf(v.z), fabsf(v.w))));
    }
#pragma unroll
    for (int o = 16; o; o >>= 1) m = fmaxf(m, __shfl_xor_sync(0xFFFFFFFFu, m, o));
    __shared__ float sm[8];
    if ((threadIdx.x & 31) == 0) sm[threadIdx.x >> 5] = m;
    __syncthreads();
    if (threadIdx.x == 0) {
        float mm = sm[0];
#pragma unroll
        for (int w = 1; w < 8; w++) mm = fmaxf(mm, sm[w]);
        atomicMax((unsigned int*)&g_maxes[slot], __float_as_uint(mm));
    }
}

__device__ __forceinline__ uint32_t pack_bf16x2(float a, float b) {
    uint32_t lo = (uint32_t)__bfloat16_as_ushort(__float2bfloat16_rn(a));
    uint32_t hi = (uint32_t)__bfloat16_as_ushort(__float2bfloat16_rn(b));
    return lo | (hi << 16);
}

// quantize fp32 -> integer-valued bf16 (round-half-even, clip [lo,127]).
// rev=1: sweep back-to-front so reads hit the L2 tail left by a preceding
// forward maxabs sweep of the same tensor (coalescing unaffected).
__global__ void quant_kernel(const float* __restrict__ src,
                             __nv_bfloat16* __restrict__ dst,
                             int n4, int npad4, int slot, float lo, int rev) {
    float mx = g_maxes[slot];
    float scale = mx / NLV;
    if (!(scale > 0.0f)) scale = 1.0f;
    float inv = 1.0f / scale;
    for (int it = blockIdx.x * blockDim.x + threadIdx.x; it < npad4;
         it += gridDim.x * blockDim.x) {
        int i = rev ? (npad4 - 1 - it) : it;
        uint32_t w0 = 0u, w1 = 0u;
        if (i < n4) {
            float4 v = ((const float4*)src)[i];
            float q0 = fminf(fmaxf(rintf(v.x * inv), lo), NLV);
            float q1 = fminf(fmaxf(rintf(v.y * inv), lo), NLV);
            float q2 = fminf(fmaxf(rintf(v.z * inv), lo), NLV);
            float q3 = fminf(fmaxf(rintf(v.w * inv), lo), NLV);
            w0 = pack_bf16x2(q0, q1);
            w1 = pack_bf16x2(q2, q3);
        }
        ((uint2*)dst)[i] = make_uint2(w0, w1);
    }
}

// split-K reduce for layer 3: sum 4 partials (fixed order), dequant + bias
__global__ void reduce3_kernel(const float* __restrict__ bias,
                               float* __restrict__ out) {
    int idx = blockIdx.x * blockDim.x + threadIdx.x;   // over 512*500 float2
    if (idx >= 512 * 500) return;
    int m = idx / 500;
    int n = (idx % 500) * 2;
    const float* p = g_part + m * 1024 + n;
    float s0 = 0.0f, s1 = 0.0f;
#pragma unroll
    for (int k = 0; k < 4; k++) {
        float2 v = *(const float2*)(p + k * (512 * 1024));
        s0 += v.x;
        s1 += v.y;
    }
    const float bs = (g_maxes[5] / NLV) * (g_maxes[3] / NLV);
    float o0 = s0 * bs + rintf(bias[n] / bs) * bs;
    float o1 = s1 * bs + rintf(bias[n + 1] / bs) * bs;
    *(float2*)(out + (size_t)m * 1000 + n) = make_float2(o0, o1);
}

// ---------------- HMMA GEMM ----------------------------------------------------
// C[M=512, Nout] = A[512,K] @ B[Npad,K]^T, bf16 in (integer-valued), fp32 accum.
// Tile 128x128x64, 3-stage cp.async pipeline, 8 warps (64x32 warp tiles).
constexpr int BM = 128, BN = 128, BK = 64, STAGES = 3, NTHREADS = 256;
constexpr int STAGE_BYTES = (BM * BK + BN * BK) * 2;   // 32768
constexpr int B_OFS = BM * BK * 2;                     // 16384

__global__ void __launch_bounds__(NTHREADS, 1)
gemm_q_kernel(const __nv_bfloat16* __restrict__ A,
              const __nv_bfloat16* __restrict__ B,
              const float* __restrict__ bias, float* __restrict__ out,
              int K, int Nout, int relu, int maxslot, int sa_slot, int sw_slot,
              int NK, int raw, int ostride) {
    extern __shared__ char smem_raw[];
    const uint32_t sb = smem_u32(smem_raw);

    const int tid = threadIdx.x;
    const int lane = tid & 31;
    const int wid = tid >> 5;
    const int wm = wid & 1;        // 2 m-blocks of 64
    const int wn = wid >> 1;       // 4 n-blocks of 32
    const int m0 = blockIdx.y * BM;
    const int n0 = blockIdx.x * BN;
    const size_t k_ofs = (size_t)blockIdx.z * NK * BK;
    float* outp = raw ? (out + (size_t)blockIdx.z * (512 * 1024)) : out;

    // ---- global->shared mapping: 2048 x 16B chunks / 256 threads = 8 each ----
    uint32_t s_st[8];
    const __nv_bfloat16* g_st[8];
#pragma unroll
    for (int i = 0; i < 8; i++) {
        int li = i * NTHREADS + tid;
        int isA = (li < 1024);
        int idx = li & 1023;
        int row = idx >> 3;            // 0..127
        int c = idx & 7;               // 16B chunk within 128B row
        s_st[i] = (uint32_t)((isA ? 0 : B_OFS) + row * 128 +
                             ((c ^ (row & 7)) << 4));
        g_st[i] = (isA ? (A + (size_t)(m0 + row) * K)
                       : (B + (size_t)(n0 + row) * K)) + k_ofs + c * 8;
    }

    // prologue loads
#pragma unroll
    for (int st = 0; st < 2; st++) {
        if (st < NK) {
            uint32_t base = sb + (uint32_t)(st % STAGES) * STAGE_BYTES;
#pragma unroll
            for (int i = 0; i < 8; i++)
                cp_async16(base + s_st[i], g_st[i] + (size_t)st * BK);
            CP_COMMIT();
        }
    }

    // ---- ldmatrix per-lane base addresses (within stage) ----
    const int r = lane & 7;
    const int g = lane >> 3;
    uint32_t a_row[4];
    int a_rx[4];
#pragma unroll
    for (int mi = 0; mi < 4; mi++) {
        int row = wm * 64 + mi * 16 + (g & 1) * 8 + r;
        a_row[mi] = (uint32_t)(row * 128);
        a_rx[mi] = row & 7;
    }
    uint32_t b_row[2];
    int b_rx[2];
#pragma unroll
    for (int p = 0; p < 2; p++) {
        int row = wn * 32 + p * 16 + (g >> 1) * 8 + r;
        b_row[p] = (uint32_t)(B_OFS + row * 128);
        b_rx[p] = row & 7;
    }

    float acc[4][4][4];
#pragma unroll
    for (int mi = 0; mi < 4; mi++)
#pragma unroll
        for (int ni = 0; ni < 4; ni++)
#pragma unroll
            for (int e = 0; e < 4; e++) acc[mi][ni][e] = 0.0f;

#pragma unroll 1
    for (int kc = 0; kc < NK; kc++) {
        if (kc + 2 < NK) {
            uint32_t base = sb + (uint32_t)((kc + 2) % STAGES) * STAGE_BYTES;
#pragma unroll
            for (int i = 0; i < 8; i++)
                cp_async16(base + s_st[i], g_st[i] + (size_t)(kc + 2) * BK);
            CP_COMMIT();
        }
        int rem = NK - 1 - kc;
        if (rem >= 2)      asm volatile("cp.async.wait_group 2;" ::: "memory");
        else if (rem == 1) asm volatile("cp.async.wait_group 1;" ::: "memory");
        else               asm volatile("cp.async.wait_group 0;" ::: "memory");
        __syncthreads();

        const uint32_t stage = sb + (uint32_t)(kc % STAGES) * STAGE_BYTES;
#pragma unroll
        for (int s = 0; s < 4; s++) {
            uint32_t af[4][4];
#pragma unroll
            for (int mi = 0; mi < 4; mi++) {
                int chunk = 2 * s + (g >> 1);
                LDSM4(af[mi], stage + a_row[mi] +
                              (uint32_t)((chunk ^ a_rx[mi]) << 4));
            }
            uint32_t bf[2][4];
#pragma unroll
            for (int p = 0; p < 2; p++) {
                int chunk = 2 * s + (g & 1);
                LDSM4(bf[p], stage + b_row[p] +
                             (uint32_t)((chunk ^ b_rx[p]) << 4));
            }
#pragma unroll
            for (int mi = 0; mi < 4; mi++) {
#pragma unroll
                for (int p = 0; p < 2; p++) {
                    MMA16816(acc[mi][2 * p],     af[mi], bf[p][0], bf[p][1]);
                    MMA16816(acc[mi][2 * p + 1], af[mi], bf[p][2], bf[p][3]);
                }
            }
        }
        __syncthreads();
    }

    // ---- epilogue ----
    if (raw) {
#pragma unroll
        for (int mi = 0; mi < 4; mi++) {
#pragma unroll
            for (int half = 0; half < 2; half++) {
                int m = m0 + wm * 64 + mi * 16 + (lane >> 2) + half * 8;
#pragma unroll
                for (int ni = 0; ni < 4; ni++) {
                    int n = n0 + wn * 32 + ni * 8 + (lane & 3) * 2;
                    *(float2*)(outp + (size_t)m * ostride + n) =
                        make_float2(acc[mi][ni][half * 2 + 0],
                                    acc[mi][ni][half * 2 + 1]);
                }
            }
        }
        return;
    }

    const float sa = g_maxes[sa_slot] / NLV;
    const float sw = g_maxes[sw_slot] / NLV;
    const float bs = sa * sw;
    float lmax = 0.0f;

    float bq[4][2];
#pragma unroll
    for (int ni = 0; ni < 4; ni++) {
        int n = n0 + wn * 32 + ni * 8 + (lane & 3) * 2;
#pragma unroll
        for (int e = 0; e < 2; e++)
            bq[ni][e] = (n + e < Nout) ? rintf(bias[n + e] / bs) * bs : 0.0f;
    }

#pragma unroll
    for (int mi = 0; mi < 4; mi++) {
#pragma unroll
        for (int half = 0; half < 2; half++) {
            int m = m0 + wm * 64 + mi * 16 + (lane >> 2) + half * 8;
#pragma unroll
            for (int ni = 0; ni < 4; ni++) {
                int n = n0 + wn * 32 + ni * 8 + (lane & 3) * 2;
                if (n < Nout) {
                    float v0 = acc[mi][ni][half * 2 + 0] * bs + bq[ni][0];
                    float v1 = acc[mi][ni][half * 2 + 1] * bs + bq[ni][1];
                    if (relu) { v0 = fmaxf(v0, 0.0f); v1 = fmaxf(v1, 0.0f); }
                    *(float2*)(outp + (size_t)m * ostride + n) =
                        make_float2(v0, v1);
                    lmax = fmaxf(lmax, fmaxf(fabsf(v0), fabsf(v1)));
                }
            }
        }
    }
    if (maxslot >= 0) {
#pragma unroll
        for (int o = 16; o; o >>= 1)
            lmax = fmaxf(lmax, __shfl_xor_sync(0xFFFFFFFFu, lmax, o));
        if (lane == 0)
            atomicMax((unsigned int*)&g_maxes[maxslot], __float_as_uint(lmax));
    }
}

// ---------------- launch -------------------------------------------------------
extern "C" void kernel_launch(void* const* d_in, const int* in_sizes, int n_in,
                              void* d_out, int out_size) {
    const float* x  = (const float*)d_in[0];
    const float* w1 = (const float*)d_in[1];
    const float* b1 = (const float*)d_in[2];
    const float* w2 = (const float*)d_in[3];
    const float* b2 = (const float*)d_in[4];
    const float* w3 = (const float*)d_in[5];
    const float* b3 = (const float*)d_in[6];
    float* out = (float*)d_out;

    void *p_xq, *p_w1q, *p_w2q, *p_w3q, *p_h, *p_hq, *p_part;
    cudaGetSymbolAddress(&p_xq, g_xq);
    cudaGetSymbolAddress(&p_w1q, g_w1q);
    cudaGetSymbolAddress(&p_w2q, g_w2q);
    cudaGetSymbolAddress(&p_w3q, g_w3q);
    cudaGetSymbolAddress(&p_h, g_h);
    cudaGetSymbolAddress(&p_hq, g_hq);
    cudaGetSymbolAddress(&p_part, g_part);

    const int SMEM = STAGES * STAGE_BYTES;   // 98304
    cudaFuncSetAttribute(gemm_q_kernel,
                         cudaFuncAttributeMaxDynamicSharedMemorySize, SMEM);

    const int RB = 1184;  // 8 * 148 SMs, grid-stride

    cudaStream_t s1;
    cudaStreamCreateWithFlags(&s1, cudaStreamNonBlocking);
    cudaEvent_t e_init, e_x, e_w1, e_aux;
    cudaEventCreateWithFlags(&e_init, cudaEventDisableTiming);
    cudaEventCreateWithFlags(&e_x, cudaEventDisableTiming);
    cudaEventCreateWithFlags(&e_w1, cudaEventDisableTiming);
    cudaEventCreateWithFlags(&e_aux, cudaEventDisableTiming);

    init_maxes_kernel<<<1, 32>>>();
    cudaEventRecord(e_init, 0);

    // s0 critical path: w1 aux (quant sweeps REVERSED -> reads hit L2 tail
    // left by the forward maxabs sweep; ~120 MB of the 151 MB re-read)
    maxabs_kernel<<<RB, 256>>>(w1, (4096 * 9216) / 4, 1);
    quant_kernel<<<RB, 256>>>(w1, (__nv_bfloat16*)p_w1q,
                              (4096 * 9216) / 4, (4096 * 9216) / 4, 1,
                              -127.0f, 1);
    cudaEventRecord(e_w1, 0);

    // s1: x aux concurrent with w1 aux
    cudaStreamWaitEvent(s1, e_init, 0);
    maxabs_kernel<<<RB, 256, 0, s1>>>(x, (512 * 9216) / 4, 0);
    quant_kernel<<<RB, 256, 0, s1>>>(x, (__nv_bfloat16*)p_xq,
                                     (512 * 9216) / 4, (512 * 9216) / 4, 0,
                                     -128.0f, 1);
    cudaEventRecord(e_x, s1);

    // GEMM1
    cudaStreamWaitEvent(0, e_x, 0);
    gemm_q_kernel<<<dim3(32, 4, 1), NTHREADS, SMEM>>>(
        (const __nv_bfloat16*)p_xq, (const __nv_bfloat16*)p_w1q, b1,
        (float*)p_h, 9216, 4096, 1, 4, 0, 1, 9216 / 64, 0, 4096);

    // s1: w2/w3 aux under GEMM1 (starts when GEMM1 can start)
    cudaStreamWaitEvent(s1, e_w1, 0);
    maxabs_kernel<<<RB, 256, 0, s1>>>(w2, (4096 * 4096) / 4, 2);
    quant_kernel<<<RB, 256, 0, s1>>>(w2, (__nv_bfloat16*)p_w2q,
                                     (4096 * 4096) / 4, (4096 * 4096) / 4, 2,
                                     -127.0f, 1);
    maxabs_kernel<<<RB, 256, 0, s1>>>(w3, (1000 * 4096) / 4, 3);
    quant_kernel<<<RB, 256, 0, s1>>>(w3, (__nv_bfloat16*)p_w3q,
                                     (1000 * 4096) / 4, (1024 * 4096) / 4, 3,
                                     -127.0f, 1);
    cudaEventRecord(e_aux, s1);

    quant_kernel<<<RB, 256>>>((const float*)p_h, (__nv_bfloat16*)p_hq,
                              (512 * 4096) / 4, (512 * 4096) / 4, 4,
                              -128.0f, 0);

    // GEMM2 needs w2q (and downstream GEMM3 needs w3q)
    cudaStreamWaitEvent(0, e_aux, 0);
    gemm_q_kernel<<<dim3(32, 4, 1), NTHREADS, SMEM>>>(
        (const __nv_bfloat16*)p_hq, (const __nv_bfloat16*)p_w2q, b2,
        (float*)p_h, 4096, 4096, 1, 5, 4, 2, 4096 / 64, 0, 4096);
    quant_kernel<<<RB, 256>>>((const float*)p_h, (__nv_bfloat16*)p_hq,
                              (512 * 4096) / 4, (512 * 4096) / 4, 5,
                              -128.0f, 0);

    // Layer 3: split-K=4 raw partials (8x4x4 = 128 CTAs), then reduce
    gemm_q_kernel<<<dim3(8, 4, 4), NTHREADS, SMEM>>>(
        (const __nv_bfloat16*)p_hq, (const __nv_bfloat16*)p_w3q, b3,
        (float*)p_part, 4096, 1024, 0, -1, 5, 3, (4096 / 64) / 4, 1, 1024);
    reduce3_kernel<<<(512 * 500 + 255) / 256, 256>>>(b3, out);

    cudaEventDestroy(e_init);
    cudaEventDestroy(e_x);
    cudaEventDestroy(e_w1);
    cudaEventDestroy(e_aux);
    cudaStreamDestroy(s1);
}

// round 16
// speedup vs baseline: 2.1833x; 1.0201x over previous
#include <cuda_runtime.h>
#include <cuda_bf16.h>
#include <cstdint>

#define NLV 127.0f

// ---------------- scratch (__device__ globals) -------------------------------
__device__ float g_maxes[8];                       // 0:x 1:w1 2:w2 3:w3 4:h1 5:h2
__device__ __nv_bfloat16 g_xq[512 * 9216];
__device__ __nv_bfloat16 g_w1q[4096 * 9216];
__device__ __nv_bfloat16 g_w2q[4096 * 4096];
__device__ __nv_bfloat16 g_w3q[1024 * 4096];       // padded 1000 -> 1024 rows
__device__ float g_h[512 * 4096];
__device__ __nv_bfloat16 g_hq[512 * 4096];
__device__ float g_part[4 * 512 * 1024];           // split-K partials for layer 3

// ---------------- helpers ----------------------------------------------------
__device__ __forceinline__ uint32_t smem_u32(const void* p) {
    uint32_t a;
    asm("{ .reg .u64 t; cvta.to.shared.u64 t, %1; cvt.u32.u64 %0, t; }"
        : "=r"(a) : "l"(p));
    return a;
}

__device__ __forceinline__ void cp_async16(uint32_t saddr, const void* g) {
    asm volatile("cp.async.cg.shared.global [%0], [%1], 16;"
                 :: "r"(saddr), "l"(g) : "memory");
}

#define CP_COMMIT() asm volatile("cp.async.commit_group;" ::: "memory")

#define LDSM4(R, addr)                                                          \
    asm volatile("ldmatrix.sync.aligned.m8n8.x4.shared.b16 "                    \
                 "{%0, %1, %2, %3}, [%4];"                                      \
                 : "=r"((R)[0]), "=r"((R)[1]), "=r"((R)[2]), "=r"((R)[3])       \
                 : "r"(addr))

#define MMA16816(C, A, B0, B1)                                                  \
    asm volatile("mma.sync.aligned.m16n8k16.row.col.f32.bf16.bf16.f32 "         \
                 "{%0, %1, %2, %3}, {%4, %5, %6, %7}, {%8, %9}, "               \
                 "{%0, %1, %2, %3};"                                            \
                 : "+f"((C)[0]), "+f"((C)[1]), "+f"((C)[2]), "+f"((C)[3])       \
                 : "r"((A)[0]), "r"((A)[1]), "r"((A)[2]), "r"((A)[3]),          \
                   "r"(B0), "r"(B1))

__device__ __forceinline__ float max4(float4 v) {
    return fmaxf(fmaxf(fabsf(v.x), fabsf(v.y)), fmaxf(fabsf(v.z), fabsf(v.w)));
}

__device__ __forceinline__ uint32_t pack_bf16x2(float a, float b) {
    uint32_t lo = (uint32_t)__bfloat16_as_ushort(__float2bfloat16_rn(a));
    uint32_t hi = (uint32_t)__bfloat16_as_ushort(__float2bfloat16_rn(b));
    return lo | (hi << 16);
}

// ---------------- small kernels ----------------------------------------------
__global__ void init_maxes_kernel() {
    if (threadIdx.x < 8) g_maxes[threadIdx.x] = 0.0f;
}

// max|.| over n8 pairs of float4 (32B contiguous per thread per iter)
__global__ void maxabs_kernel(const float* __restrict__ src, int n8, int slot) {
    float m = 0.0f;
    const float4* s4 = (const float4*)src;
    for (int i = blockIdx.x * blockDim.x + threadIdx.x; i < n8;
         i += gridDim.x * blockDim.x) {
        float4 v0 = s4[2 * (size_t)i];
        float4 v1 = s4[2 * (size_t)i + 1];
        m = fmaxf(m, fmaxf(max4(v0), max4(v1)));
    }
#pragma unroll
    for (int o = 16; o; o >>= 1) m = fmaxf(m, __shfl_xor_sync(0xFFFFFFFFu, m, o));
    __shared__ float sm[8];
    if ((threadIdx.x & 31) == 0) sm[threadIdx.x >> 5] = m;
    __syncthreads();
    if (threadIdx.x == 0) {
        float mm = sm[0];
#pragma unroll
        for (int w = 1; w < 8; w++) mm = fmaxf(mm, sm[w]);
        atomicMax((unsigned int*)&g_maxes[slot], __float_as_uint(mm));
    }
}

// quantize fp32 -> integer-valued bf16 (round-half-even, clip [lo,127]).
// 8 floats (32B) per thread per iter; uint4 stores. Pads [n8,npad8) with 0.
__global__ void quant_kernel(const float* __restrict__ src,
                             __nv_bfloat16* __restrict__ dst,
                             int n8, int npad8, int slot, float lo) {
    float mx = g_maxes[slot];
    float scale = mx / NLV;
    if (!(scale > 0.0f)) scale = 1.0f;
    float inv = 1.0f / scale;
    const float4* s4 = (const float4*)src;
    for (int i = blockIdx.x * blockDim.x + threadIdx.x; i < npad8;
         i += gridDim.x * blockDim.x) {
        uint4 w = make_uint4(0u, 0u, 0u, 0u);
        if (i < n8) {
            float4 v0 = s4[2 * (size_t)i];
            float4 v1 = s4[2 * (size_t)i + 1];
            float c[8] = {v0.x, v0.y, v0.z, v0.w, v1.x, v1.y, v1.z, v1.w};
#pragma unroll
            for (int j = 0; j < 8; j++)
                c[j] = fminf(fmaxf(rintf(c[j] * inv), lo), NLV);
            w.x = pack_bf16x2(c[0], c[1]);
            w.y = pack_bf16x2(c[2], c[3]);
            w.z = pack_bf16x2(c[4], c[5]);
            w.w = pack_bf16x2(c[6], c[7]);
        }
        ((uint4*)dst)[i] = w;
    }
}

// split-K reduce for layer 3: sum 4 partials (fixed order), dequant + bias
__global__ void reduce3_kernel(const float* __restrict__ bias,
                               float* __restrict__ out) {
    int idx = blockIdx.x * blockDim.x + threadIdx.x;   // over 512*500 float2
    if (idx >= 512 * 500) return;
    int m = idx / 500;
    int n = (idx % 500) * 2;
    const float* p = g_part + m * 1024 + n;
    float s0 = 0.0f, s1 = 0.0f;
#pragma unroll
    for (int k = 0; k < 4; k++) {
        float2 v = *(const float2*)(p + k * (512 * 1024));
        s0 += v.x;
        s1 += v.y;
    }
    const float bs = (g_maxes[5] / NLV) * (g_maxes[3] / NLV);
    float o0 = s0 * bs + rintf(bias[n] / bs) * bs;
    float o1 = s1 * bs + rintf(bias[n + 1] / bs) * bs;
    *(float2*)(out + (size_t)m * 1000 + n) = make_float2(o0, o1);
}

// ---------------- HMMA GEMM ----------------------------------------------------
// C[M=512, Nout] = A[512,K] @ B[Npad,K]^T, bf16 in (integer-valued), fp32 accum.
// Tile 128x128x64, 3-stage cp.async pipeline, 8 warps (64x32 warp tiles).
constexpr int BM = 128, BN = 128, BK = 64, STAGES = 3, NTHREADS = 256;
constexpr int STAGE_BYTES = (BM * BK + BN * BK) * 2;   // 32768
constexpr int B_OFS = BM * BK * 2;                     // 16384

__global__ void __launch_bounds__(NTHREADS, 1)
gemm_q_kernel(const __nv_bfloat16* __restrict__ A,
              const __nv_bfloat16* __restrict__ B,
              const float* __restrict__ bias, float* __restrict__ out,
              int K, int Nout, int relu, int maxslot, int sa_slot, int sw_slot,
              int NK, int raw, int ostride) {
    extern __shared__ char smem_raw[];
    const uint32_t sb = smem_u32(smem_raw);

    const int tid = threadIdx.x;
    const int lane = tid & 31;
    const int wid = tid >> 5;
    const int wm = wid & 1;        // 2 m-blocks of 64
    const int wn = wid >> 1;       // 4 n-blocks of 32
    const int m0 = blockIdx.y * BM;
    const int n0 = blockIdx.x * BN;
    const size_t k_ofs = (size_t)blockIdx.z * NK * BK;
    float* outp = raw ? (out + (size_t)blockIdx.z * (512 * 1024)) : out;

    // ---- global->shared mapping: 2048 x 16B chunks / 256 threads = 8 each ----
    uint32_t s_st[8];
    const __nv_bfloat16* g_st[8];
#pragma unroll
    for (int i = 0; i < 8; i++) {
        int li = i * NTHREADS + tid;
        int isA = (li < 1024);
        int idx = li & 1023;
        int row = idx >> 3;            // 0..127
        int c = idx & 7;               // 16B chunk within 128B row
        s_st[i] = (uint32_t)((isA ? 0 : B_OFS) + row * 128 +
                             ((c ^ (row & 7)) << 4));
        g_st[i] = (isA ? (A + (size_t)(m0 + row) * K)
                       : (B + (size_t)(n0 + row) * K)) + k_ofs + c * 8;
    }

    // prologue loads
#pragma unroll
    for (int st = 0; st < 2; st++) {
        if (st < NK) {
            uint32_t base = sb + (uint32_t)(st % STAGES) * STAGE_BYTES;
#pragma unroll
            for (int i = 0; i < 8; i++)
                cp_async16(base + s_st[i], g_st[i] + (size_t)st * BK);
            CP_COMMIT();
        }
    }

    // ---- ldmatrix per-lane base addresses (within stage) ----
    const int r = lane & 7;
    const int g = lane >> 3;
    uint32_t a_row[4];
    int a_rx[4];
#pragma unroll
    for (int mi = 0; mi < 4; mi++) {
        int row = wm * 64 + mi * 16 + (g & 1) * 8 + r;
        a_row[mi] = (uint32_t)(row * 128);
        a_rx[mi] = row & 7;
    }
    uint32_t b_row[2];
    int b_rx[2];
#pragma unroll
    for (int p = 0; p < 2; p++) {
        int row = wn * 32 + p * 16 + (g >> 1) * 8 + r;
        b_row[p] = (uint32_t)(B_OFS + row * 128);
        b_rx[p] = row & 7;
    }

    float acc[4][4][4];
#pragma unroll
    for (int mi = 0; mi < 4; mi++)
#pragma unroll
        for (int ni = 0; ni < 4; ni++)
#pragma unroll
            for (int e = 0; e < 4; e++) acc[mi][ni][e] = 0.0f;

#pragma unroll 1
    for (int kc = 0; kc < NK; kc++) {
        if (kc + 2 < NK) {
            uint32_t base = sb + (uint32_t)((kc + 2) % STAGES) * STAGE_BYTES;
#pragma unroll
            for (int i = 0; i < 8; i++)
                cp_async16(base + s_st[i], g_st[i] + (size_t)(kc + 2) * BK);
            CP_COMMIT();
        }
        int rem = NK - 1 - kc;
        if (rem >= 2)      asm volatile("cp.async.wait_group 2;" ::: "memory");
        else if (rem == 1) asm volatile("cp.async.wait_group 1;" ::: "memory");
        else               asm volatile("cp.async.wait_group 0;" ::: "memory");
        __syncthreads();

        const uint32_t stage = sb + (uint32_t)(kc % STAGES) * STAGE_BYTES;
#pragma unroll
        for (int s = 0; s < 4; s++) {
            uint32_t af[4][4];
#pragma unroll
            for (int mi = 0; mi < 4; mi++) {
                int chunk = 2 * s + (g >> 1);
                LDSM4(af[mi], stage + a_row[mi] +
                              (uint32_t)((chunk ^ a_rx[mi]) << 4));
            }
            uint32_t bf[2][4];
#pragma unroll
            for (int p = 0; p < 2; p++) {
                int chunk = 2 * s + (g & 1);
                LDSM4(bf[p], stage + b_row[p] +
                             (uint32_t)((chunk ^ b_rx[p]) << 4));
            }
#pragma unroll
            for (int mi = 0; mi < 4; mi++) {
#pragma unroll
                for (int p = 0; p < 2; p++) {
                    MMA16816(acc[mi][2 * p],     af[mi], bf[p][0], bf[p][1]);
                    MMA16816(acc[mi][2 * p + 1], af[mi], bf[p][2], bf[p][3]);
                }
            }
        }
        __syncthreads();
    }

    // ---- epilogue ----
    if (raw) {
#pragma unroll
        for (int mi = 0; mi < 4; mi++) {
#pragma unroll
            for (int half = 0; half < 2; half++) {
                int m = m0 + wm * 64 + mi * 16 + (lane >> 2) + half * 8;
#pragma unroll
                for (int ni = 0; ni < 4; ni++) {
                    int n = n0 + wn * 32 + ni * 8 + (lane & 3) * 2;
                    *(float2*)(outp + (size_t)m * ostride + n) =
                        make_float2(acc[mi][ni][half * 2 + 0],
                                    acc[mi][ni][half * 2 + 1]);
                }
            }
        }
        return;
    }

    const float sa = g_maxes[sa_slot] / NLV;
    const float sw = g_maxes[sw_slot] / NLV;
    const float bs = sa * sw;
    float lmax = 0.0f;

    float bq[4][2];
#pragma unroll
    for (int ni = 0; ni < 4; ni++) {
        int n = n0 + wn * 32 + ni * 8 + (lane & 3) * 2;
#pragma unroll
        for (int e = 0; e < 2; e++)
            bq[ni][e] = (n + e < Nout) ? rintf(bias[n + e] / bs) * bs : 0.0f;
    }

#pragma unroll
    for (int mi = 0; mi < 4; mi++) {
#pragma unroll
        for (int half = 0; half < 2; half++) {
            int m = m0 + wm * 64 + mi * 16 + (lane >> 2) + half * 8;
#pragma unroll
            for (int ni = 0; ni < 4; ni++) {
                int n = n0 + wn * 32 + ni * 8 + (lane & 3) * 2;
                if (n < Nout) {
                    float v0 = acc[mi][ni][half * 2 + 0] * bs + bq[ni][0];
                    float v1 = acc[mi][ni][half * 2 + 1] * bs + bq[ni][1];
                    if (relu) { v0 = fmaxf(v0, 0.0f); v1 = fmaxf(v1, 0.0f); }
                    *(float2*)(outp + (size_t)m * ostride + n) =
                        make_float2(v0, v1);
                    lmax = fmaxf(lmax, fmaxf(fabsf(v0), fabsf(v1)));
                }
            }
        }
    }
    if (maxslot >= 0) {
#pragma unroll
        for (int o = 16; o; o >>= 1)
            lmax = fmaxf(lmax, __shfl_xor_sync(0xFFFFFFFFu, lmax, o));
        if (lane == 0)
            atomicMax((unsigned int*)&g_maxes[maxslot], __float_as_uint(lmax));
    }
}

// ---------------- launch -------------------------------------------------------
extern "C" void kernel_launch(void* const* d_in, const int* in_sizes, int n_in,
                              void* d_out, int out_size) {
    const float* x  = (const float*)d_in[0];
    const float* w1 = (const float*)d_in[1];
    const float* b1 = (const float*)d_in[2];
    const float* w2 = (const float*)d_in[3];
    const float* b2 = (const float*)d_in[4];
    const float* w3 = (const float*)d_in[5];
    const float* b3 = (const float*)d_in[6];
    float* out = (float*)d_out;

    void *p_xq, *p_w1q, *p_w2q, *p_w3q, *p_h, *p_hq, *p_part;
    cudaGetSymbolAddress(&p_xq, g_xq);
    cudaGetSymbolAddress(&p_w1q, g_w1q);
    cudaGetSymbolAddress(&p_w2q, g_w2q);
    cudaGetSymbolAddress(&p_w3q, g_w3q);
    cudaGetSymbolAddress(&p_h, g_h);
    cudaGetSymbolAddress(&p_hq, g_hq);
    cudaGetSymbolAddress(&p_part, g_part);

    const int SMEM = STAGES * STAGE_BYTES;   // 98304
    cudaFuncSetAttribute(gemm_q_kernel,
                         cudaFuncAttributeMaxDynamicSharedMemorySize, SMEM);

    const int RB = 1184;  // 8 * 148 SMs, grid-stride

    cudaStream_t s1;
    cudaStreamCreateWithFlags(&s1, cudaStreamNonBlocking);
    cudaEvent_t e_init, e_x, e_w1, e_aux;
    cudaEventCreateWithFlags(&e_init, cudaEventDisableTiming);
    cudaEventCreateWithFlags(&e_x, cudaEventDisableTiming);
    cudaEventCreateWithFlags(&e_w1, cudaEventDisableTiming);
    cudaEventCreateWithFlags(&e_aux, cudaEventDisableTiming);

    init_maxes_kernel<<<1, 32>>>();
    cudaEventRecord(e_init, 0);

    // s0 critical path: w1 aux
    maxabs_kernel<<<RB, 256>>>(w1, (4096 * 9216) / 8, 1);
    quant_kernel<<<RB, 256>>>(w1, (__nv_bfloat16*)p_w1q,
                              (4096 * 9216) / 8, (4096 * 9216) / 8, 1, -127.0f);
    cudaEventRecord(e_w1, 0);

    // s1: x aux concurrent with w1 aux
    cudaStreamWaitEvent(s1, e_init, 0);
    maxabs_kernel<<<RB, 256, 0, s1>>>(x, (512 * 9216) / 8, 0);
    quant_kernel<<<RB, 256, 0, s1>>>(x, (__nv_bfloat16*)p_xq,
                                     (512 * 9216) / 8, (512 * 9216) / 8, 0,
                                     -128.0f);
    cudaEventRecord(e_x, s1);

    // GEMM1
    cudaStreamWaitEvent(0, e_x, 0);
    gemm_q_kernel<<<dim3(32, 4, 1), NTHREADS, SMEM>>>(
        (const __nv_bfloat16*)p_xq, (const __nv_bfloat16*)p_w1q, b1,
        (float*)p_h, 9216, 4096, 1, 4, 0, 1, 9216 / 64, 0, 4096);

    // s1: w2/w3 aux under GEMM1 (starts when GEMM1 can start)
    cudaStreamWaitEvent(s1, e_w1, 0);
    maxabs_kernel<<<RB, 256, 0, s1>>>(w2, (4096 * 4096) / 8, 2);
    quant_kernel<<<RB, 256, 0, s1>>>(w2, (__nv_bfloat16*)p_w2q,
                                     (4096 * 4096) / 8, (4096 * 4096) / 8, 2,
                                     -127.0f);
    maxabs_kernel<<<RB, 256, 0, s1>>>(w3, (1000 * 4096) / 8, 3);
    quant_kernel<<<RB, 256, 0, s1>>>(w3, (__nv_bfloat16*)p_w3q,
                                     (1000 * 4096) / 8, (1024 * 4096) / 8, 3,
                                     -127.0f);
    cudaEventRecord(e_aux, s1);

    quant_kernel<<<RB, 256>>>((const float*)p_h, (__nv_bfloat16*)p_hq,
                              (512 * 4096) / 8, (512 * 4096) / 8, 4, -128.0f);

    // GEMM2 needs w2q (and downstream GEMM3 needs w3q)
    cudaStreamWaitEvent(0, e_aux, 0);
    gemm_q_kernel<<<dim3(32, 4, 1), NTHREADS, SMEM>>>(
        (const __nv_bfloat16*)p_hq, (const __nv_bfloat16*)p_w2q, b2,
        (float*)p_h, 4096, 4096, 1, 5, 4, 2, 4096 / 64, 0, 4096);
    quant_kernel<<<RB, 256>>>((const float*)p_h, (__nv_bfloat16*)p_hq,
                              (512 * 4096) / 8, (512 * 4096) / 8, 5, -128.0f);

    // Layer 3: split-K=4 raw partials (8x4x4 = 128 CTAs), then reduce
    gemm_q_kernel<<<dim3(8, 4, 4), NTHREADS, SMEM>>>(
        (const __nv_bfloat16*)p_hq, (const __nv_bfloat16*)p_w3q, b3,
        (float*)p_part, 4096, 1024, 0, -1, 5, 3, (4096 / 64) / 4, 1, 1024);
    reduce3_kernel<<<(512 * 500 + 255) / 256, 256>>>(b3, out);

    cudaEventDestroy(e_init);
    cudaEventDestroy(e_x);
    cudaEventDestroy(e_w1);
    cudaEventDestroy(e_aux);
    cudaStreamDestroy(s1);
}